// round 1
// baseline (speedup 1.0000x reference)
#include <cuda_runtime.h>
#include <cstdint>

// ============================================================================
// Problem constants
//   B=8, N=256 (queries), M=256 (memory), T=512, H=16, D=64, DIM=1024
//   INNER = 1024, 3*INNER = 3072, MAXLEN=512 -> R rows = 1024
//   Key structural facts:
//     * masks restrict attention to j in [i, i+256]  (window of 257)
//     * shift s(i,j) = (j-256-i) mod 1024 = ((j-i)+768) & 1023, delta=j-i in [0,256]
// ============================================================================

__device__ float g_RW[1024u * 1024u];            // R @ Wkr
__device__ float g_q [8u * 16u * 256u * 64u];    // [bh][i][d]
__device__ float g_k [8u * 16u * 512u * 64u];    // [bh][j][d]
__device__ float g_v [8u * 16u * 512u * 64u];    // [bh][j][d]
__device__ float g_P [8u * 16u * 256u * 257u];   // [bh][i][delta]
__device__ float g_c [8u * 16u * 512u];          // [bh][j]   u . k
__device__ float g_dt[16u * 257u];               // [h][delta] v . RW[s]
__device__ float g_O [8u * 256u * 1024u];        // [b][i][h*64+d] attn output

// ============================================================================
// Generic SGEMM: C[M,N] = A[M,K] @ B[K,N], row major, M%128==0, N%128==0, K%8==0
// 128x128 block tile, BK=8, 256 threads, 8x8 per thread.
// ============================================================================
__global__ __launch_bounds__(256) void sgemm128(
    const float* __restrict__ A, const float* __restrict__ B,
    float* __restrict__ C, int M, int N, int K)
{
    __shared__ float As[8 * 128];
    __shared__ float Bs[8 * 128];
    int tid = threadIdx.x;
    int tx = tid & 15, ty = tid >> 4;
    int bx = blockIdx.x, by = blockIdx.y;

    float acc[8][8] = {};

    int arow = tid >> 1;
    int akk  = (tid & 1) * 4;
    const float* Ap = A + (size_t)(by * 128 + arow) * K + akk;
    int bkk = tid >> 5;
    int bc  = (tid * 4) & 127;
    const float* Bp = B + (size_t)bkk * N + bx * 128 + bc;

    for (int k0 = 0; k0 < K; k0 += 8) {
        float4 av = *(const float4*)(Ap + k0);
        float4 bv = *(const float4*)(Bp + (size_t)k0 * N);
        As[(akk + 0) * 128 + arow] = av.x;
        As[(akk + 1) * 128 + arow] = av.y;
        As[(akk + 2) * 128 + arow] = av.z;
        As[(akk + 3) * 128 + arow] = av.w;
        *(float4*)&Bs[bkk * 128 + bc] = bv;
        __syncthreads();
#pragma unroll
        for (int kk = 0; kk < 8; kk++) {
            float a[8], b[8];
            *(float4*)&a[0] = *(const float4*)&As[kk * 128 + ty * 8];
            *(float4*)&a[4] = *(const float4*)&As[kk * 128 + ty * 8 + 4];
            *(float4*)&b[0] = *(const float4*)&Bs[kk * 128 + tx * 8];
            *(float4*)&b[4] = *(const float4*)&Bs[kk * 128 + tx * 8 + 4];
#pragma unroll
            for (int i = 0; i < 8; i++)
#pragma unroll
                for (int j = 0; j < 8; j++)
                    acc[i][j] = fmaf(a[i], b[j], acc[i][j]);
        }
        __syncthreads();
    }
#pragma unroll
    for (int i = 0; i < 8; i++)
#pragma unroll
        for (int j = 0; j < 8; j++)
            C[(size_t)(by * 128 + ty * 8 + i) * N + bx * 128 + tx * 8 + j] = acc[i][j];
}

// ============================================================================
// qkv GEMM: rows are cat(h, x) gathered; output scattered to g_q/g_k/g_v with
// [bh][t][d] layout.  M=4096 (b*512+t), N=3072, K=1024.
// Blocks producing q (cols<1024) for memory rows (t<256) are skipped (unused).
// ============================================================================
__global__ __launch_bounds__(256) void qkv_gemm128(
    const float* __restrict__ x, const float* __restrict__ h,
    const float* __restrict__ Wqkv)
{
    int bx = blockIdx.x, by = blockIdx.y;
    if (bx < 8 && (by & 3) < 2) return;   // q-section for memory rows: never read

    __shared__ float As[8 * 128];
    __shared__ float Bs[8 * 128];
    int tid = threadIdx.x;
    int tx = tid & 15, ty = tid >> 4;
    float acc[8][8] = {};

    int arow = tid >> 1;
    int akk  = (tid & 1) * 4;
    int gr = by * 128 + arow;
    int b  = gr >> 9, t = gr & 511;
    const float* Ap = ((t < 256) ? (h + ((size_t)b * 256 + t) * 1024)
                                 : (x + ((size_t)b * 256 + (t - 256)) * 1024)) + akk;
    int bkk = tid >> 5;
    int bc  = (tid * 4) & 127;
    const float* Bp = Wqkv + (size_t)bkk * 3072 + bx * 128 + bc;

    for (int k0 = 0; k0 < 1024; k0 += 8) {
        float4 av = *(const float4*)(Ap + k0);
        float4 bv = *(const float4*)(Bp + (size_t)k0 * 3072);
        As[(akk + 0) * 128 + arow] = av.x;
        As[(akk + 1) * 128 + arow] = av.y;
        As[(akk + 2) * 128 + arow] = av.z;
        As[(akk + 3) * 128 + arow] = av.w;
        *(float4*)&Bs[bkk * 128 + bc] = bv;
        __syncthreads();
#pragma unroll
        for (int kk = 0; kk < 8; kk++) {
            float a[8], bb[8];
            *(float4*)&a[0]  = *(const float4*)&As[kk * 128 + ty * 8];
            *(float4*)&a[4]  = *(const float4*)&As[kk * 128 + ty * 8 + 4];
            *(float4*)&bb[0] = *(const float4*)&Bs[kk * 128 + tx * 8];
            *(float4*)&bb[4] = *(const float4*)&Bs[kk * 128 + tx * 8 + 4];
#pragma unroll
            for (int i = 0; i < 8; i++)
#pragma unroll
                for (int j = 0; j < 8; j++)
                    acc[i][j] = fmaf(a[i], bb[j], acc[i][j]);
        }
        __syncthreads();
    }
    // scatter epilogue
#pragma unroll
    for (int i = 0; i < 8; i++) {
        int grr = by * 128 + ty * 8 + i;
        int bb2 = grr >> 9, tt = grr & 511;
#pragma unroll
        for (int j = 0; j < 8; j++) {
            int gc = bx * 128 + tx * 8 + j;
            int sec = gc >> 10, c2 = gc & 1023, hh = c2 >> 6, d = c2 & 63;
            float vv = acc[i][j];
            if (sec == 0) {
                if (tt >= 256)
                    g_q[(((size_t)bb2 * 16 + hh) * 256 + (tt - 256)) * 64 + d] = vv;
            } else if (sec == 1) {
                g_k[(((size_t)bb2 * 16 + hh) * 512 + tt) * 64 + d] = vv;
            } else {
                g_v[(((size_t)bb2 * 16 + hh) * 512 + tt) * 64 + d] = vv;
            }
        }
    }
}

// ============================================================================
// P GEMM: P[bh][i][t] = sum_d q[bh][i][d] * RW[(t+768)&1023][h*64+d], t<257
// grid (5 t-tiles, 4 i-tiles, 128 bh), 64x64 tile, 4x4 per thread.
// ============================================================================
__global__ __launch_bounds__(256) void p_gemm()
{
    __shared__ float sQ[64 * 65];
    __shared__ float sR[64 * 65];
    int tt = blockIdx.x, it = blockIdx.y, bh = blockIdx.z;
    int hh = bh & 15;
    int tid = threadIdx.x, tx = tid & 15, ty = tid >> 4;
    int i0 = it * 64, t0 = tt * 64;

    for (int e = tid; e < 4096; e += 256) {
        int row = e >> 6, d = e & 63;
        sQ[row * 65 + d] = g_q[((size_t)bh * 256 + i0 + row) * 64 + d];
        int tr = t0 + row;
        sR[row * 65 + d] = (tr < 257)
            ? g_RW[(size_t)((tr + 768) & 1023) * 1024 + hh * 64 + d] : 0.f;
    }
    __syncthreads();

    float acc[4][4] = {};
#pragma unroll 16
    for (int d = 0; d < 64; d++) {
        float a[4], b[4];
#pragma unroll
        for (int r = 0; r < 4; r++) a[r] = sQ[(ty * 4 + r) * 65 + d];
#pragma unroll
        for (int c = 0; c < 4; c++) b[c] = sR[(tx * 4 + c) * 65 + d];
#pragma unroll
        for (int r = 0; r < 4; r++)
#pragma unroll
            for (int c = 0; c < 4; c++)
                acc[r][c] = fmaf(a[r], b[c], acc[r][c]);
    }
#pragma unroll
    for (int r = 0; r < 4; r++)
#pragma unroll
        for (int c = 0; c < 4; c++) {
            int t = t0 + tx * 4 + c;
            if (t < 257)
                g_P[((size_t)bh * 256 + i0 + ty * 4 + r) * 257 + t] = acc[r][c];
        }
}

// ============================================================================
// c[bh][j] = u . k[bh][j]      (warp per row)
// ============================================================================
__global__ __launch_bounds__(256) void cterm_kernel(const float* __restrict__ u)
{
    int row  = blockIdx.x * 8 + (threadIdx.x >> 5);
    int lane = threadIdx.x & 31;
    float s = u[lane] * g_k[(size_t)row * 64 + lane]
            + u[lane + 32] * g_k[(size_t)row * 64 + lane + 32];
#pragma unroll
    for (int o = 16; o; o >>= 1) s += __shfl_xor_sync(0xffffffffu, s, o);
    if (lane == 0) g_c[row] = s;
}

// d[h][t] = v . RW[(t+768)&1023][h*64:...]
__global__ __launch_bounds__(256) void dterm_kernel(const float* __restrict__ v)
{
    int row = blockIdx.x * 8 + (threadIdx.x >> 5);
    if (row >= 16 * 257) return;
    int hh = row / 257, t = row % 257;
    int lane = threadIdx.x & 31;
    const float* src = g_RW + (size_t)((t + 768) & 1023) * 1024 + hh * 64;
    float s = v[lane] * src[lane] + v[lane + 32] * src[lane + 32];
#pragma unroll
    for (int o = 16; o; o >>= 1) s += __shfl_xor_sync(0xffffffffu, s, o);
    if (lane == 0) g_dt[row] = s;
}

// ============================================================================
// Fused windowed attention. grid (4 i-tiles, 128 bh), 256 threads.
// For i-tile [i0, i0+64): keys span [i0, i0+320) (window j in [i, i+256]).
// Full-row softmax done in smem (64 x 320 scores).
// Output written transposed to g_O[b][i][h*64+d].
// ============================================================================
#define SSTR 321
__global__ __launch_bounds__(256) void attn_kernel()
{
    extern __shared__ float sm[];
    float* sQ  = sm;                 // [d][i] stride 65 : sQ[d*65+i]
    float* sKV = sm + 4160;          // phase1: sK[d*65+j]; phase3: sV[j*64+d]
    float* sS  = sm + 8320;          // [64][SSTR]

    int it = blockIdx.x, bh = blockIdx.y;
    int hh = bh & 15, bb = bh >> 4;
    int i0 = it * 64;
    int tid = threadIdx.x, tx = tid & 15, ty = tid >> 4;

    for (int e = tid; e < 4096; e += 256) {
        int i = e >> 6, d = e & 63;
        sQ[d * 65 + i] = g_q[((size_t)bh * 256 + i0 + i) * 64 + d];
    }

    // ---- phase 1: scores ----
    for (int jt = 0; jt < 5; jt++) {
        int jbase = i0 + jt * 64;
        __syncthreads();
        for (int e = tid; e < 4096; e += 256) {
            int j = e >> 6, d = e & 63;
            sKV[d * 65 + j] = g_k[((size_t)bh * 512 + jbase + j) * 64 + d];
        }
        __syncthreads();
        float acc[4][4] = {};
#pragma unroll 16
        for (int d = 0; d < 64; d++) {
            float a[4], b[4];
#pragma unroll
            for (int r = 0; r < 4; r++) a[r] = sQ[d * 65 + ty * 4 + r];
#pragma unroll
            for (int c = 0; c < 4; c++) b[c] = sKV[d * 65 + tx * 4 + c];
#pragma unroll
            for (int r = 0; r < 4; r++)
#pragma unroll
                for (int c = 0; c < 4; c++)
                    acc[r][c] = fmaf(a[r], b[c], acc[r][c]);
        }
#pragma unroll
        for (int r = 0; r < 4; r++)
#pragma unroll
            for (int c = 0; c < 4; c++) {
                int i  = ty * 4 + r, jj = tx * 4 + c;
                int ig = i0 + i,     j  = jbase + jj;
                int delta = j - ig;
                float s = -1e30f;
                if (delta >= 0 && delta <= 256) {
                    s = (acc[r][c]
                         + g_P[((size_t)bh * 256 + ig) * 257 + delta]
                         + g_c[(size_t)bh * 512 + j]
                         + g_dt[hh * 257 + delta]) * 0.125f;
                }
                sS[i * SSTR + jt * 64 + jj] = s;
            }
    }
    __syncthreads();

    // ---- phase 2: softmax per row over 320 cols ----
    {
        int warp = tid >> 5, lane = tid & 31;
        for (int r = warp; r < 64; r += 8) {
            float m = -1e30f;
            for (int c = lane; c < 320; c += 32) m = fmaxf(m, sS[r * SSTR + c]);
#pragma unroll
            for (int o = 16; o; o >>= 1) m = fmaxf(m, __shfl_xor_sync(0xffffffffu, m, o));
            float sum = 0.f;
            for (int c = lane; c < 320; c += 32) {
                float e = __expf(sS[r * SSTR + c] - m);
                sS[r * SSTR + c] = e;
                sum += e;
            }
#pragma unroll
            for (int o = 16; o; o >>= 1) sum += __shfl_xor_sync(0xffffffffu, sum, o);
            float inv = 1.f / sum;
            for (int c = lane; c < 320; c += 32) sS[r * SSTR + c] *= inv;
        }
    }

    // ---- phase 3: O = attn @ V ----
    float o[4][4] = {};
    for (int jt = 0; jt < 5; jt++) {
        int jbase = i0 + jt * 64;
        __syncthreads();
        for (int e = tid; e < 4096; e += 256)
            sKV[e] = g_v[((size_t)bh * 512 + jbase) * 64 + e];
        __syncthreads();
#pragma unroll 8
        for (int jj = 0; jj < 64; jj++) {
            float p[4], w[4];
#pragma unroll
            for (int r = 0; r < 4; r++) p[r] = sS[(ty * 4 + r) * SSTR + jt * 64 + jj];
#pragma unroll
            for (int c = 0; c < 4; c++) w[c] = sKV[jj * 64 + tx * 4 + c];
#pragma unroll
            for (int r = 0; r < 4; r++)
#pragma unroll
                for (int c = 0; c < 4; c++)
                    o[r][c] = fmaf(p[r], w[c], o[r][c]);
        }
    }
#pragma unroll
    for (int r = 0; r < 4; r++)
#pragma unroll
        for (int c = 0; c < 4; c++) {
            int ig = i0 + ty * 4 + r, d = tx * 4 + c;
            g_O[((size_t)bb * 256 + ig) * 1024 + hh * 64 + d] = o[r][c];
        }
}

// ============================================================================
// kernel_launch
// ============================================================================
extern "C" void kernel_launch(void* const* d_in, const int* in_sizes, int n_in,
                              void* d_out, int out_size)
{
    const float* x    = (const float*)d_in[0];
    const float* h    = (const float*)d_in[1];
    const float* Wqkv = (const float*)d_in[2];
    const float* Wkr  = (const float*)d_in[3];
    const float* R    = (const float*)d_in[4];
    const float* u    = (const float*)d_in[5];
    const float* v    = (const float*)d_in[6];
    const float* Wout = (const float*)d_in[7];
    float* out = (float*)d_out;

    float *pRW = nullptr, *pO = nullptr;
    cudaGetSymbolAddress((void**)&pRW, g_RW);
    cudaGetSymbolAddress((void**)&pO,  g_O);

    // 1. RW = R @ Wkr  (1024x1024x1024)
    sgemm128<<<dim3(8, 8), 256>>>(R, Wkr, pRW, 1024, 1024, 1024);

    // 2. qkv = cat(h,x) @ Wqkv -> g_q/g_k/g_v
    qkv_gemm128<<<dim3(24, 32), 256>>>(x, h, Wqkv);

    // 3. P = q @ Rsub^T   (needs 1 & 2)
    p_gemm<<<dim3(5, 4, 128), 256>>>();

    // 4. bias terms
    cterm_kernel<<<8192, 256>>>(u);
    dterm_kernel<<<514, 256>>>(v);

    // 5. fused windowed attention
    static const int kAttnSmem = (4160 + 4160 + 64 * SSTR) * 4;  // 115456 B
    cudaFuncSetAttribute(attn_kernel, cudaFuncAttributeMaxDynamicSharedMemorySize,
                         kAttnSmem);
    attn_kernel<<<dim3(4, 128), 256, kAttnSmem>>>();

    // 6. out = O @ Wout   (2048x1024x1024)
    sgemm128<<<dim3(8, 16), 256>>>(pO, Wout, out, 2048, 1024, 1024);
}

// round 3
// speedup vs baseline: 2.2648x; 2.2648x over previous
#include <cuda_runtime.h>
#include <cuda_bf16.h>
#include <cstdint>

// ============================================================================
// Problem: B=8, N=256, M=256, T=512, H=16, D=64, DIM=1024.
// Window: j in [i, i+256]; shift s = ((j-i)+768) & 1023.
// Round 3: dense GEMMs on warp-level mma.sync bf16 (portable PTX; tcgen05 is
// not available because the harness PTX-targets compute_103 without 'a').
// bf16 split: x ~= hi + lo; x*y ~= hi*hi + hi*lo + lo*hi (fp32 accum).
// ============================================================================

__device__ float g_RW[1024u * 1024u];            // R @ Wkr
__device__ float g_q [8u * 16u * 256u * 64u];    // [bh][i][d]
__device__ float g_k [8u * 16u * 512u * 64u];    // [bh][j][d]
__device__ float g_v [8u * 16u * 512u * 64u];    // [bh][j][d]
__device__ float g_P [8u * 16u * 256u * 257u];   // [bh][i][delta]
__device__ float g_c [8u * 16u * 512u];          // [bh][j]
__device__ float g_dt[16u * 257u];               // [h][delta]
__device__ float g_O [8u * 256u * 1024u];        // [b][i][h*64+d]

__device__ __nv_bfloat16 g_Ah[4096u * 1024u];
__device__ __nv_bfloat16 g_Al[4096u * 1024u];
__device__ __nv_bfloat16 g_Bh[3072u * 1024u];    // W^T rows [N][K]
__device__ __nv_bfloat16 g_Bl[3072u * 1024u];

// ============================================================================
// PTX helpers (portable: mma.sync / ldmatrix / cp.async)
// ============================================================================
__device__ __forceinline__ uint32_t smem_u32(const void* p) {
    uint32_t a;
    asm("{ .reg .u64 t; cvta.to.shared.u64 t, %1; cvt.u32.u64 %0, t; }"
        : "=r"(a) : "l"(p));
    return a;
}
__device__ __forceinline__ void cp16(uint32_t saddr, const void* g) {
    asm volatile("cp.async.cg.shared.global [%0], [%1], 16;"
                 :: "r"(saddr), "l"(g) : "memory");
}
#define CP_COMMIT() asm volatile("cp.async.commit_group;" ::: "memory")
#define CP_WAIT1()  asm volatile("cp.async.wait_group 1;" ::: "memory")
#define CP_WAIT0()  asm volatile("cp.async.wait_group 0;" ::: "memory")

__device__ __forceinline__ void ldsm4(uint32_t* r, uint32_t addr) {
    asm volatile("ldmatrix.sync.aligned.m8n8.x4.shared.b16 {%0,%1,%2,%3}, [%4];"
                 : "=r"(r[0]), "=r"(r[1]), "=r"(r[2]), "=r"(r[3]) : "r"(addr));
}
__device__ __forceinline__ void mma16816(float* c, const uint32_t* a,
                                         const uint32_t* b) {
    asm volatile(
        "mma.sync.aligned.m16n8k16.row.col.f32.bf16.bf16.f32 "
        "{%0,%1,%2,%3}, {%4,%5,%6,%7}, {%8,%9}, {%0,%1,%2,%3};"
        : "+f"(c[0]), "+f"(c[1]), "+f"(c[2]), "+f"(c[3])
        : "r"(a[0]), "r"(a[1]), "r"(a[2]), "r"(a[3]), "r"(b[0]), "r"(b[1]));
}

// ============================================================================
// mma GEMM: C[M,N] = A[M,1024] @ B^T, B^T stored [N,1024].
// CTA 128x128, BK=32, warp tile 64x32, double-buffered cp.async smem.
// smem row stride 80B (64B data + 16B pad) -> conflict-free ldmatrix.
// mode 0: C[gr*ldc+gc]. mode 1: scatter to g_q/g_k/g_v (skip unused q tiles).
// ============================================================================
#define MG_ARR 10240                      // 128 rows * 80B
#define MG_STG (4 * MG_ARR)               // Ah, Al, Bh, Bl
#define MG_SMEM (2 * MG_STG)              // 81920 B

__device__ __forceinline__ void mg_scatter2(int gr, int gc, float v0, float v1) {
    int b = gr >> 9, tt = gr & 511;
    int sec = gc >> 10, c2 = gc & 1023, hh = c2 >> 6, d = c2 & 63;
    float2 vv = make_float2(v0, v1);
    if (sec == 0) {
        if (tt >= 256)
            *(float2*)&g_q[(((size_t)b * 16 + hh) * 256 + (tt - 256)) * 64 + d] = vv;
    } else if (sec == 1) {
        *(float2*)&g_k[(((size_t)b * 16 + hh) * 512 + tt) * 64 + d] = vv;
    } else {
        *(float2*)&g_v[(((size_t)b * 16 + hh) * 512 + tt) * 64 + d] = vv;
    }
}

__global__ __launch_bounds__(256) void mma_gemm(
    const __nv_bfloat16* __restrict__ Ah, const __nv_bfloat16* __restrict__ Al,
    const __nv_bfloat16* __restrict__ Bh, const __nv_bfloat16* __restrict__ Bl,
    float* __restrict__ C, int ldc, int mode)
{
    int bx = blockIdx.x, by = blockIdx.y;
    if (mode == 1 && bx < 8 && (by & 3) < 2) return;   // q for memory rows

    extern __shared__ char smc[];
    uint32_t sb = smem_u32(smc);
    int tid = threadIdx.x, lane = tid & 31, wid = tid >> 5;
    int wm = wid >> 2, wn = wid & 3;                    // warp grid 2 x 4

    const __nv_bfloat16* gA[2] = { Ah, Al };
    const __nv_bfloat16* gB[2] = { Bh, Bl };

    // per-thread cp.async slots: 2048 16B-chunks per stage, 8 per thread
    // idx = tid + l*256 ; arr = idx>>9 (0 Ah,1 Al,2 Bh,3 Bl); e=idx&511
    // row = e>>2 ; c = e&3
    auto load_stage = [&](int s, int kt) {
#pragma unroll
        for (int l = 0; l < 8; l++) {
            int idx = tid + l * 256;
            int arr = idx >> 9, e = idx & 511;
            int row = e >> 2, c = e & 3;
            const __nv_bfloat16* gp = (arr < 2)
                ? gA[arr] + (size_t)(by * 128 + row) * 1024 + kt * 32 + c * 8
                : gB[arr - 2] + (size_t)(bx * 128 + row) * 1024 + kt * 32 + c * 8;
            cp16(sb + s * MG_STG + arr * MG_ARR + (uint32_t)(row * 80 + c * 16), gp);
        }
        CP_COMMIT();
    };

    float acc[16][4];
#pragma unroll
    for (int i = 0; i < 16; i++)
#pragma unroll
        for (int j = 0; j < 4; j++) acc[i][j] = 0.f;

    load_stage(0, 0);

    for (int kt = 0; kt < 32; kt++) {
        if (kt + 1 < 32) { load_stage((kt + 1) & 1, kt + 1); CP_WAIT1(); }
        else             { CP_WAIT0(); }
        __syncthreads();

        uint32_t stg = sb + (kt & 1) * MG_STG;
#pragma unroll
        for (int kk = 0; kk < 2; kk++) {
            // A fragments: 4 m-tiles, hi+lo
            uint32_t afh[4][4], afl[4][4];
            {
                int row = wm * 64 + (lane & 15);
                int c   = kk * 2 + (lane >> 4);
                uint32_t off = (uint32_t)(row * 80 + c * 16);
#pragma unroll
                for (int t = 0; t < 4; t++) {
                    ldsm4(afh[t], stg + 0 * MG_ARR + off + t * (16 * 80));
                    ldsm4(afl[t], stg + 1 * MG_ARR + off + t * (16 * 80));
                }
            }
            // B fragments: 4 n-tiles (two ldsm4 each of hi/lo)
            uint32_t bfh[8], bfl[8];
            {
                int n = wn * 32 + ((lane >> 4) * 8 + (lane & 7));
                int c = kk * 2 + ((lane >> 3) & 1);
                uint32_t off = (uint32_t)(n * 80 + c * 16);
                ldsm4(&bfh[0], stg + 2 * MG_ARR + off);
                ldsm4(&bfh[4], stg + 2 * MG_ARR + off + 16 * 80);
                ldsm4(&bfl[0], stg + 3 * MG_ARR + off);
                ldsm4(&bfl[4], stg + 3 * MG_ARR + off + 16 * 80);
            }
#pragma unroll
            for (int t = 0; t < 4; t++)
#pragma unroll
                for (int n = 0; n < 4; n++) {
                    float* cc = acc[t * 4 + n];
                    mma16816(cc, afh[t], &bfh[n * 2]);
                    mma16816(cc, afh[t], &bfl[n * 2]);
                    mma16816(cc, afl[t], &bfh[n * 2]);
                }
        }
        __syncthreads();
    }

    // epilogue
#pragma unroll
    for (int t = 0; t < 4; t++)
#pragma unroll
        for (int n = 0; n < 4; n++) {
            int gr = by * 128 + wm * 64 + t * 16 + (lane >> 2);
            int gc = bx * 128 + wn * 32 + n * 8 + (lane & 3) * 2;
            float* cc = acc[t * 4 + n];
            if (mode == 0) {
                *(float2*)&C[(size_t)gr * ldc + gc]       = make_float2(cc[0], cc[1]);
                *(float2*)&C[(size_t)(gr + 8) * ldc + gc] = make_float2(cc[2], cc[3]);
            } else {
                mg_scatter2(gr, gc, cc[0], cc[1]);
                mg_scatter2(gr + 8, gc, cc[2], cc[3]);
            }
        }
}

// ============================================================================
// Conversion kernels
// ============================================================================
__device__ __forceinline__ unsigned short bfb(__nv_bfloat16 x) {
    return *reinterpret_cast<unsigned short*>(&x);
}
__device__ __forceinline__ void split4(float4 v, uint2& H, uint2& L) {
    __nv_bfloat16 h0 = __float2bfloat16(v.x), h1 = __float2bfloat16(v.y);
    __nv_bfloat16 h2 = __float2bfloat16(v.z), h3 = __float2bfloat16(v.w);
    __nv_bfloat16 l0 = __float2bfloat16(v.x - __bfloat162float(h0));
    __nv_bfloat16 l1 = __float2bfloat16(v.y - __bfloat162float(h1));
    __nv_bfloat16 l2 = __float2bfloat16(v.z - __bfloat162float(h2));
    __nv_bfloat16 l3 = __float2bfloat16(v.w - __bfloat162float(h3));
    H.x = (uint32_t)bfb(h0) | ((uint32_t)bfb(h1) << 16);
    H.y = (uint32_t)bfb(h2) | ((uint32_t)bfb(h3) << 16);
    L.x = (uint32_t)bfb(l0) | ((uint32_t)bfb(l1) << 16);
    L.y = (uint32_t)bfb(l2) | ((uint32_t)bfb(l3) << 16);
}

__global__ __launch_bounds__(256) void conv_split(
    const float4* __restrict__ src, uint2* __restrict__ hi,
    uint2* __restrict__ lo, int n4)
{
    int i = blockIdx.x * 256 + threadIdx.x;
    if (i >= n4) return;
    uint2 H, L;
    split4(src[i], H, L);
    hi[i] = H; lo[i] = L;
}

__global__ __launch_bounds__(256) void conv_split_cat(
    const float* __restrict__ x, const float* __restrict__ h,
    uint2* __restrict__ hi, uint2* __restrict__ lo)
{
    int i = blockIdx.x * 256 + threadIdx.x;
    int row = i >> 8, c4 = i & 255;
    int b = row >> 9, t = row & 511;
    const float4* src = (const float4*)((t < 256)
        ? (h + ((size_t)b * 256 + t) * 1024)
        : (x + ((size_t)b * 256 + (t - 256)) * 1024));
    uint2 H, L;
    split4(src[c4], H, L);
    hi[i] = H; lo[i] = L;
}

__global__ __launch_bounds__(256) void conv_split_T(
    const float* __restrict__ W, __nv_bfloat16* __restrict__ Th,
    __nv_bfloat16* __restrict__ Tl, int N)
{
    __shared__ float ts[32][33];
    int n0 = blockIdx.x * 32, k0 = blockIdx.y * 32;
    int tx = threadIdx.x, ty = threadIdx.y;  // (32,8)
#pragma unroll
    for (int r = 0; r < 32; r += 8)
        ts[ty + r][tx] = W[(size_t)(k0 + ty + r) * N + n0 + tx];
    __syncthreads();
#pragma unroll
    for (int r = 0; r < 32; r += 8) {
        float v = ts[tx][ty + r];
        __nv_bfloat16 hh = __float2bfloat16(v);
        __nv_bfloat16 ll = __float2bfloat16(v - __bfloat162float(hh));
        size_t o = (size_t)(n0 + ty + r) * 1024 + k0 + tx;
        Th[o] = hh; Tl[o] = ll;
    }
}

// ============================================================================
// P GEMM (fp32), bias terms, fused attention — unchanged from round 1
// ============================================================================
__global__ __launch_bounds__(256) void p_gemm()
{
    __shared__ float sQ[64 * 65];
    __shared__ float sR[64 * 65];
    int tt = blockIdx.x, it = blockIdx.y, bh = blockIdx.z;
    int hh = bh & 15;
    int tid = threadIdx.x, tx = tid & 15, ty = tid >> 4;
    int i0 = it * 64, t0 = tt * 64;

    for (int e = tid; e < 4096; e += 256) {
        int row = e >> 6, d = e & 63;
        sQ[row * 65 + d] = g_q[((size_t)bh * 256 + i0 + row) * 64 + d];
        int tr = t0 + row;
        sR[row * 65 + d] = (tr < 257)
            ? g_RW[(size_t)((tr + 768) & 1023) * 1024 + hh * 64 + d] : 0.f;
    }
    __syncthreads();

    float acc[4][4] = {};
#pragma unroll 16
    for (int d = 0; d < 64; d++) {
        float a[4], b[4];
#pragma unroll
        for (int r = 0; r < 4; r++) a[r] = sQ[(ty * 4 + r) * 65 + d];
#pragma unroll
        for (int c = 0; c < 4; c++) b[c] = sR[(tx * 4 + c) * 65 + d];
#pragma unroll
        for (int r = 0; r < 4; r++)
#pragma unroll
            for (int c = 0; c < 4; c++)
                acc[r][c] = fmaf(a[r], b[c], acc[r][c]);
    }
#pragma unroll
    for (int r = 0; r < 4; r++)
#pragma unroll
        for (int c = 0; c < 4; c++) {
            int t = t0 + tx * 4 + c;
            if (t < 257)
                g_P[((size_t)bh * 256 + i0 + ty * 4 + r) * 257 + t] = acc[r][c];
        }
}

__global__ __launch_bounds__(256) void cterm_kernel(const float* __restrict__ u)
{
    int row  = blockIdx.x * 8 + (threadIdx.x >> 5);
    int lane = threadIdx.x & 31;
    float s = u[lane] * g_k[(size_t)row * 64 + lane]
            + u[lane + 32] * g_k[(size_t)row * 64 + lane + 32];
#pragma unroll
    for (int o = 16; o; o >>= 1) s += __shfl_xor_sync(0xffffffffu, s, o);
    if (lane == 0) g_c[row] = s;
}

__global__ __launch_bounds__(256) void dterm_kernel(const float* __restrict__ v)
{
    int row = blockIdx.x * 8 + (threadIdx.x >> 5);
    if (row >= 16 * 257) return;
    int hh = row / 257, t = row % 257;
    int lane = threadIdx.x & 31;
    const float* src = g_RW + (size_t)((t + 768) & 1023) * 1024 + hh * 64;
    float s = v[lane] * src[lane] + v[lane + 32] * src[lane + 32];
#pragma unroll
    for (int o = 16; o; o >>= 1) s += __shfl_xor_sync(0xffffffffu, s, o);
    if (lane == 0) g_dt[row] = s;
}

#define SSTR 321
__global__ __launch_bounds__(256) void attn_kernel()
{
    extern __shared__ float smf[];
    float* sQ  = smf;
    float* sKV = smf + 4160;
    float* sS  = smf + 8320;

    int it = blockIdx.x, bh = blockIdx.y;
    int hh = bh & 15, bb = bh >> 4;
    int i0 = it * 64;
    int tid = threadIdx.x, tx = tid & 15, ty = tid >> 4;

    for (int e = tid; e < 4096; e += 256) {
        int i = e >> 6, d = e & 63;
        sQ[d * 65 + i] = g_q[((size_t)bh * 256 + i0 + i) * 64 + d];
    }

    for (int jt = 0; jt < 5; jt++) {
        int jbase = i0 + jt * 64;
        __syncthreads();
        for (int e = tid; e < 4096; e += 256) {
            int j = e >> 6, d = e & 63;
            sKV[d * 65 + j] = g_k[((size_t)bh * 512 + jbase + j) * 64 + d];
        }
        __syncthreads();
        float acc[4][4] = {};
#pragma unroll 16
        for (int d = 0; d < 64; d++) {
            float a[4], b[4];
#pragma unroll
            for (int r = 0; r < 4; r++) a[r] = sQ[d * 65 + ty * 4 + r];
#pragma unroll
            for (int c = 0; c < 4; c++) b[c] = sKV[d * 65 + tx * 4 + c];
#pragma unroll
            for (int r = 0; r < 4; r++)
#pragma unroll
                for (int c = 0; c < 4; c++)
                    acc[r][c] = fmaf(a[r], b[c], acc[r][c]);
        }
#pragma unroll
        for (int r = 0; r < 4; r++)
#pragma unroll
            for (int c = 0; c < 4; c++) {
                int i  = ty * 4 + r, jj = tx * 4 + c;
                int ig = i0 + i,     j  = jbase + jj;
                int delta = j - ig;
                float s = -1e30f;
                if (delta >= 0 && delta <= 256) {
                    s = (acc[r][c]
                         + g_P[((size_t)bh * 256 + ig) * 257 + delta]
                         + g_c[(size_t)bh * 512 + j]
                         + g_dt[hh * 257 + delta]) * 0.125f;
                }
                sS[i * SSTR + jt * 64 + jj] = s;
            }
    }
    __syncthreads();

    {
        int warp = tid >> 5, lane = tid & 31;
        for (int r = warp; r < 64; r += 8) {
            float m = -1e30f;
            for (int c = lane; c < 320; c += 32) m = fmaxf(m, sS[r * SSTR + c]);
#pragma unroll
            for (int o = 16; o; o >>= 1) m = fmaxf(m, __shfl_xor_sync(0xffffffffu, m, o));
            float sum = 0.f;
            for (int c = lane; c < 320; c += 32) {
                float e = __expf(sS[r * SSTR + c] - m);
                sS[r * SSTR + c] = e;
                sum += e;
            }
#pragma unroll
            for (int o = 16; o; o >>= 1) sum += __shfl_xor_sync(0xffffffffu, sum, o);
            float inv = 1.f / sum;
            for (int c = lane; c < 320; c += 32) sS[r * SSTR + c] *= inv;
        }
    }

    float o[4][4] = {};
    for (int jt = 0; jt < 5; jt++) {
        int jbase = i0 + jt * 64;
        __syncthreads();
        for (int e = tid; e < 4096; e += 256)
            sKV[e] = g_v[((size_t)bh * 512 + jbase) * 64 + e];
        __syncthreads();
#pragma unroll 8
        for (int jj = 0; jj < 64; jj++) {
            float p[4], w[4];
#pragma unroll
            for (int r = 0; r < 4; r++) p[r] = sS[(ty * 4 + r) * SSTR + jt * 64 + jj];
#pragma unroll
            for (int c = 0; c < 4; c++) w[c] = sKV[jj * 64 + tx * 4 + c];
#pragma unroll
            for (int r = 0; r < 4; r++)
#pragma unroll
                for (int c = 0; c < 4; c++)
                    o[r][c] = fmaf(p[r], w[c], o[r][c]);
        }
    }
#pragma unroll
    for (int r = 0; r < 4; r++)
#pragma unroll
        for (int c = 0; c < 4; c++) {
            int ig = i0 + ty * 4 + r, d = tx * 4 + c;
            g_O[((size_t)bb * 256 + ig) * 1024 + hh * 64 + d] = o[r][c];
        }
}

// ============================================================================
// kernel_launch
// ============================================================================
extern "C" void kernel_launch(void* const* d_in, const int* in_sizes, int n_in,
                              void* d_out, int out_size)
{
    const float* x    = (const float*)d_in[0];
    const float* h    = (const float*)d_in[1];
    const float* Wqkv = (const float*)d_in[2];
    const float* Wkr  = (const float*)d_in[3];
    const float* R    = (const float*)d_in[4];
    const float* u    = (const float*)d_in[5];
    const float* v    = (const float*)d_in[6];
    const float* Wout = (const float*)d_in[7];
    float* out = (float*)d_out;

    float *pRW = nullptr, *pO = nullptr;
    __nv_bfloat16 *pAh = nullptr, *pAl = nullptr, *pBh = nullptr, *pBl = nullptr;
    cudaGetSymbolAddress((void**)&pRW, g_RW);
    cudaGetSymbolAddress((void**)&pO,  g_O);
    cudaGetSymbolAddress((void**)&pAh, g_Ah);
    cudaGetSymbolAddress((void**)&pAl, g_Al);
    cudaGetSymbolAddress((void**)&pBh, g_Bh);
    cudaGetSymbolAddress((void**)&pBl, g_Bl);

    cudaFuncSetAttribute(mma_gemm, cudaFuncAttributeMaxDynamicSharedMemorySize,
                         MG_SMEM);
    static const int kAttnSmem = (4160 + 4160 + 64 * SSTR) * 4;
    cudaFuncSetAttribute(attn_kernel, cudaFuncAttributeMaxDynamicSharedMemorySize,
                         kAttnSmem);

    // --- RW = R @ Wkr ---
    conv_split_T<<<dim3(32, 32), dim3(32, 8)>>>(Wkr, pBh, pBl, 1024);
    conv_split<<<1024, 256>>>((const float4*)R, (uint2*)pAh, (uint2*)pAl, 262144);
    mma_gemm<<<dim3(8, 8), 256, MG_SMEM>>>(pAh, pAl, pBh, pBl, pRW, 1024, 0);

    // --- qkv = cat(h,x) @ Wqkv -> g_q/g_k/g_v ---
    conv_split_T<<<dim3(96, 32), dim3(32, 8)>>>(Wqkv, pBh, pBl, 3072);
    conv_split_cat<<<4096, 256>>>(x, h, (uint2*)pAh, (uint2*)pAl);
    mma_gemm<<<dim3(24, 32), 256, MG_SMEM>>>(pAh, pAl, pBh, pBl, nullptr, 0, 1);

    // --- bias terms + P ---
    p_gemm<<<dim3(5, 4, 128), 256>>>();
    cterm_kernel<<<8192, 256>>>(u);
    dterm_kernel<<<514, 256>>>(v);

    // --- fused windowed attention ---
    attn_kernel<<<dim3(4, 128), 256, kAttnSmem>>>();

    // --- out = O @ Wout ---
    conv_split<<<2048, 256>>>((const float4*)pO, (uint2*)pAh, (uint2*)pAl, 524288);
    conv_split_T<<<dim3(32, 32), dim3(32, 8)>>>(Wout, pBh, pBl, 1024);
    mma_gemm<<<dim3(8, 16), 256, MG_SMEM>>>(pAh, pAl, pBh, pBl, out, 1024, 0);
}

// round 4
// speedup vs baseline: 2.5999x; 1.1480x over previous
#include <cuda_runtime.h>
#include <cuda_bf16.h>
#include <cstdint>

// ============================================================================
// B=8, N=256, M=256, T=512, H=16, D=64, DIM=1024.
// Window: j in [i, i+256]; shift s = ((j-i)+768) & 1023.
// Round 4: everything heavy on mma.sync bf16-split (hi*hi + hi*lo + lo*hi).
// ============================================================================

__device__ float g_RW [1024u * 1024u];                 // R @ Wkr (fp32, for dterm)
__device__ __nv_bfloat16 g_RWh[1024u * 1024u];
__device__ __nv_bfloat16 g_RWl[1024u * 1024u];
__device__ __nv_bfloat16 g_qh[8u*16u*256u*64u], g_ql[8u*16u*256u*64u];
__device__ __nv_bfloat16 g_kh[8u*16u*512u*64u], g_kl[8u*16u*512u*64u];
__device__ __nv_bfloat16 g_vh[8u*16u*512u*64u], g_vl[8u*16u*512u*64u];
__device__ float g_P [8u * 16u * 256u * 257u];         // [bh][i][delta]
__device__ float g_c [8u * 16u * 512u];                // [bh][j]
__device__ float g_dt[16u * 257u];                     // [h][delta]

__device__ __nv_bfloat16 g_Ah[4096u * 1024u];
__device__ __nv_bfloat16 g_Al[4096u * 1024u];
__device__ __nv_bfloat16 g_Bh[3072u * 1024u];          // W^T rows [N][K]
__device__ __nv_bfloat16 g_Bl[3072u * 1024u];

// ============================================================================
// PTX helpers
// ============================================================================
__device__ __forceinline__ uint32_t smem_u32(const void* p) {
    uint32_t a;
    asm("{ .reg .u64 t; cvta.to.shared.u64 t, %1; cvt.u32.u64 %0, t; }"
        : "=r"(a) : "l"(p));
    return a;
}
__device__ __forceinline__ void cp16(uint32_t saddr, const void* g) {
    asm volatile("cp.async.cg.shared.global [%0], [%1], 16;"
                 :: "r"(saddr), "l"(g) : "memory");
}
#define CP_COMMIT() asm volatile("cp.async.commit_group;" ::: "memory")
#define CP_WAIT1()  asm volatile("cp.async.wait_group 1;" ::: "memory")
#define CP_WAIT0()  asm volatile("cp.async.wait_group 0;" ::: "memory")

__device__ __forceinline__ void ldsm4(uint32_t* r, uint32_t addr) {
    asm volatile("ldmatrix.sync.aligned.m8n8.x4.shared.b16 {%0,%1,%2,%3}, [%4];"
                 : "=r"(r[0]), "=r"(r[1]), "=r"(r[2]), "=r"(r[3]) : "r"(addr));
}
__device__ __forceinline__ void ldsm4t(uint32_t* r, uint32_t addr) {
    asm volatile("ldmatrix.sync.aligned.m8n8.x4.trans.shared.b16 {%0,%1,%2,%3}, [%4];"
                 : "=r"(r[0]), "=r"(r[1]), "=r"(r[2]), "=r"(r[3]) : "r"(addr));
}
__device__ __forceinline__ void mma16816(float* c, const uint32_t* a,
                                         const uint32_t* b) {
    asm volatile(
        "mma.sync.aligned.m16n8k16.row.col.f32.bf16.bf16.f32 "
        "{%0,%1,%2,%3}, {%4,%5,%6,%7}, {%8,%9}, {%0,%1,%2,%3};"
        : "+f"(c[0]), "+f"(c[1]), "+f"(c[2]), "+f"(c[3])
        : "r"(a[0]), "r"(a[1]), "r"(a[2]), "r"(a[3]), "r"(b[0]), "r"(b[1]));
}

__device__ __forceinline__ unsigned short bfb(__nv_bfloat16 x) {
    return *reinterpret_cast<unsigned short*>(&x);
}
__device__ __forceinline__ void pack2(float a, float b, uint32_t& H, uint32_t& L) {
    __nv_bfloat16 ah = __float2bfloat16(a), bh2 = __float2bfloat16(b);
    __nv_bfloat16 al = __float2bfloat16(a - __bfloat162float(ah));
    __nv_bfloat16 bl = __float2bfloat16(b - __bfloat162float(bh2));
    H = (uint32_t)bfb(ah) | ((uint32_t)bfb(bh2) << 16);
    L = (uint32_t)bfb(al) | ((uint32_t)bfb(bl) << 16);
}

// ============================================================================
// Dense mma GEMM: C[M,N] = A[M,1024] @ B^T (B^T stored [N,1024]).
// CTA 128x128, BK=32, double-buffered cp.async, 80B smem rows.
// mode 0: fp32 C. mode 1: qkv scatter -> bf16 split q/k/v.
// mode 2: fp32 C + bf16 split to g_RWh/g_RWl.
// ============================================================================
#define MG_ARR 10240
#define MG_STG (4 * MG_ARR)
#define MG_SMEM (2 * MG_STG)

__device__ __forceinline__ void qkv_scatter(int gr, int gc, float v0, float v1) {
    int b = gr >> 9, tt = gr & 511;
    int sec = gc >> 10, c2 = gc & 1023, hh = c2 >> 6, d = c2 & 63;
    uint32_t H, L; pack2(v0, v1, H, L);
    if (sec == 0) {
        if (tt >= 256) {
            size_t o = (((size_t)b * 16 + hh) * 256 + (tt - 256)) * 64 + d;
            *(uint32_t*)&g_qh[o] = H; *(uint32_t*)&g_ql[o] = L;
        }
    } else {
        size_t o = (((size_t)b * 16 + hh) * 512 + tt) * 64 + d;
        if (sec == 1) { *(uint32_t*)&g_kh[o] = H; *(uint32_t*)&g_kl[o] = L; }
        else          { *(uint32_t*)&g_vh[o] = H; *(uint32_t*)&g_vl[o] = L; }
    }
}

__global__ __launch_bounds__(256) void mma_gemm(
    const __nv_bfloat16* __restrict__ Ah, const __nv_bfloat16* __restrict__ Al,
    const __nv_bfloat16* __restrict__ Bh, const __nv_bfloat16* __restrict__ Bl,
    float* __restrict__ C, int ldc, int mode)
{
    int bx = blockIdx.x, by = blockIdx.y;
    if (mode == 1 && bx < 8 && (by & 3) < 2) return;

    extern __shared__ char smc[];
    uint32_t sb = smem_u32(smc);
    int tid = threadIdx.x, lane = tid & 31, wid = tid >> 5;
    int wm = wid >> 2, wn = wid & 3;

    const __nv_bfloat16* gA[2] = { Ah, Al };
    const __nv_bfloat16* gB[2] = { Bh, Bl };

    auto load_stage = [&](int s, int kt) {
#pragma unroll
        for (int l = 0; l < 8; l++) {
            int idx = tid + l * 256;
            int arr = idx >> 9, e = idx & 511;
            int row = e >> 2, c = e & 3;
            const __nv_bfloat16* gp = (arr < 2)
                ? gA[arr] + (size_t)(by * 128 + row) * 1024 + kt * 32 + c * 8
                : gB[arr - 2] + (size_t)(bx * 128 + row) * 1024 + kt * 32 + c * 8;
            cp16(sb + s * MG_STG + arr * MG_ARR + (uint32_t)(row * 80 + c * 16), gp);
        }
        CP_COMMIT();
    };

    float acc[16][4];
#pragma unroll
    for (int i = 0; i < 16; i++)
#pragma unroll
        for (int j = 0; j < 4; j++) acc[i][j] = 0.f;

    load_stage(0, 0);

    for (int kt = 0; kt < 32; kt++) {
        if (kt + 1 < 32) { load_stage((kt + 1) & 1, kt + 1); CP_WAIT1(); }
        else             { CP_WAIT0(); }
        __syncthreads();

        uint32_t stg = sb + (kt & 1) * MG_STG;
#pragma unroll
        for (int kk = 0; kk < 2; kk++) {
            uint32_t afh[4][4], afl[4][4];
            {
                int row = wm * 64 + (lane & 15);
                int c   = kk * 2 + (lane >> 4);
                uint32_t off = (uint32_t)(row * 80 + c * 16);
#pragma unroll
                for (int t = 0; t < 4; t++) {
                    ldsm4(afh[t], stg + 0 * MG_ARR + off + t * (16 * 80));
                    ldsm4(afl[t], stg + 1 * MG_ARR + off + t * (16 * 80));
                }
            }
            uint32_t bfh[8], bfl[8];
            {
                int n = wn * 32 + ((lane >> 4) * 8 + (lane & 7));
                int c = kk * 2 + ((lane >> 3) & 1);
                uint32_t off = (uint32_t)(n * 80 + c * 16);
                ldsm4(&bfh[0], stg + 2 * MG_ARR + off);
                ldsm4(&bfh[4], stg + 2 * MG_ARR + off + 16 * 80);
                ldsm4(&bfl[0], stg + 3 * MG_ARR + off);
                ldsm4(&bfl[4], stg + 3 * MG_ARR + off + 16 * 80);
            }
#pragma unroll
            for (int t = 0; t < 4; t++)
#pragma unroll
                for (int n = 0; n < 4; n++) {
                    float* cc = acc[t * 4 + n];
                    mma16816(cc, afh[t], &bfh[n * 2]);
                    mma16816(cc, afh[t], &bfl[n * 2]);
                    mma16816(cc, afl[t], &bfh[n * 2]);
                }
        }
        __syncthreads();
    }

#pragma unroll
    for (int t = 0; t < 4; t++)
#pragma unroll
        for (int n = 0; n < 4; n++) {
            int gr = by * 128 + wm * 64 + t * 16 + (lane >> 2);
            int gc = bx * 128 + wn * 32 + n * 8 + (lane & 3) * 2;
            float* cc = acc[t * 4 + n];
            if (mode == 0) {
                *(float2*)&C[(size_t)gr * ldc + gc]       = make_float2(cc[0], cc[1]);
                *(float2*)&C[(size_t)(gr + 8) * ldc + gc] = make_float2(cc[2], cc[3]);
            } else if (mode == 2) {
                *(float2*)&C[(size_t)gr * ldc + gc]       = make_float2(cc[0], cc[1]);
                *(float2*)&C[(size_t)(gr + 8) * ldc + gc] = make_float2(cc[2], cc[3]);
                uint32_t H, L;
                pack2(cc[0], cc[1], H, L);
                *(uint32_t*)&g_RWh[(size_t)gr * 1024 + gc] = H;
                *(uint32_t*)&g_RWl[(size_t)gr * 1024 + gc] = L;
                pack2(cc[2], cc[3], H, L);
                *(uint32_t*)&g_RWh[(size_t)(gr + 8) * 1024 + gc] = H;
                *(uint32_t*)&g_RWl[(size_t)(gr + 8) * 1024 + gc] = L;
            } else {
                qkv_scatter(gr, gc, cc[0], cc[1]);
                qkv_scatter(gr + 8, gc, cc[2], cc[3]);
            }
        }
}

// ============================================================================
// Conversion kernels
// ============================================================================
__device__ __forceinline__ void split4(float4 v, uint2& H, uint2& L) {
    uint32_t h0, l0, h1, l1;
    pack2(v.x, v.y, h0, l0);
    pack2(v.z, v.w, h1, l1);
    H.x = h0; H.y = h1; L.x = l0; L.y = l1;
}

__global__ __launch_bounds__(256) void conv_split(
    const float4* __restrict__ src, uint2* __restrict__ hi,
    uint2* __restrict__ lo, int n4)
{
    int i = blockIdx.x * 256 + threadIdx.x;
    if (i >= n4) return;
    uint2 H, L;
    split4(src[i], H, L);
    hi[i] = H; lo[i] = L;
}

__global__ __launch_bounds__(256) void conv_split_cat(
    const float* __restrict__ x, const float* __restrict__ h,
    uint2* __restrict__ hi, uint2* __restrict__ lo)
{
    int i = blockIdx.x * 256 + threadIdx.x;
    int row = i >> 8, c4 = i & 255;
    int b = row >> 9, t = row & 511;
    const float4* src = (const float4*)((t < 256)
        ? (h + ((size_t)b * 256 + t) * 1024)
        : (x + ((size_t)b * 256 + (t - 256)) * 1024));
    uint2 H, L;
    split4(src[c4], H, L);
    hi[i] = H; lo[i] = L;
}

__global__ __launch_bounds__(256) void conv_split_T(
    const float* __restrict__ W, __nv_bfloat16* __restrict__ Th,
    __nv_bfloat16* __restrict__ Tl, int N)
{
    __shared__ float ts[32][33];
    int n0 = blockIdx.x * 32, k0 = blockIdx.y * 32;
    int tx = threadIdx.x, ty = threadIdx.y;
#pragma unroll
    for (int r = 0; r < 32; r += 8)
        ts[ty + r][tx] = W[(size_t)(k0 + ty + r) * N + n0 + tx];
    __syncthreads();
#pragma unroll
    for (int r = 0; r < 32; r += 8) {
        float v = ts[tx][ty + r];
        __nv_bfloat16 hh = __float2bfloat16(v);
        __nv_bfloat16 ll = __float2bfloat16(v - __bfloat162float(hh));
        size_t o = (size_t)(n0 + ty + r) * 1024 + k0 + tx;
        Th[o] = hh; Tl[o] = ll;
    }
}

// ============================================================================
// P GEMM (mma): P[bh][i][t] = q[bh][i] . RW[(t+768)&1023][h*64:+64]
// Block: 64 i x 64 t, K=64, 8 warps (4m x 2n). grid (5, 4, 128).
// ============================================================================
#define PG_LDB 144
__global__ __launch_bounds__(256) void p_gemm_mma()
{
    __shared__ char sm[4 * 64 * PG_LDB];
    uint32_t sQh = smem_u32(sm);
    uint32_t sQl = sQh + 64 * PG_LDB;
    uint32_t sBh = sQl + 64 * PG_LDB;
    uint32_t sBl = sBh + 64 * PG_LDB;

    int tt = blockIdx.x, it = blockIdx.y, bh = blockIdx.z;
    int hh = bh & 15;
    int i0 = it * 64, t0 = tt * 64;
    int tid = threadIdx.x, lane = tid & 31, wid = tid >> 5;
    int wm = wid >> 1, wn = wid & 1;

#pragma unroll
    for (int l = 0; l < 2; l++) {
        int e = tid + l * 256;
        int row = e >> 3, c = e & 7;
        size_t qo = ((size_t)bh * 256 + i0 + row) * 64 + c * 8;
        *(uint4*)(sm + (sQh - smem_u32(sm)) + row * PG_LDB + c * 16) =
            *(const uint4*)&g_qh[qo];
        *(uint4*)(sm + (sQl - smem_u32(sm)) + row * PG_LDB + c * 16) =
            *(const uint4*)&g_ql[qo];
        int rr = (t0 + row + 768) & 1023;
        size_t bo = (size_t)rr * 1024 + hh * 64 + c * 8;
        *(uint4*)(sm + (sBh - smem_u32(sm)) + row * PG_LDB + c * 16) =
            *(const uint4*)&g_RWh[bo];
        *(uint4*)(sm + (sBl - smem_u32(sm)) + row * PG_LDB + c * 16) =
            *(const uint4*)&g_RWl[bo];
    }
    __syncthreads();

    float acc[4][4];
#pragma unroll
    for (int n = 0; n < 4; n++)
#pragma unroll
        for (int j = 0; j < 4; j++) acc[n][j] = 0.f;

#pragma unroll
    for (int kk = 0; kk < 4; kk++) {
        uint32_t afh[4], afl[4];
        {
            int row = wm * 16 + (lane & 15);
            uint32_t off = (uint32_t)(row * PG_LDB + kk * 32 + (lane >> 4) * 16);
            ldsm4(afh, sQh + off);
            ldsm4(afl, sQl + off);
        }
        uint32_t bfh[8], bfl[8];
        {
            int n = wn * 32 + ((lane >> 4) * 8 + (lane & 7));
            uint32_t off = (uint32_t)(n * PG_LDB + kk * 32 + ((lane >> 3) & 1) * 16);
            ldsm4(&bfh[0], sBh + off);
            ldsm4(&bfh[4], sBh + off + 16 * PG_LDB);
            ldsm4(&bfl[0], sBl + off);
            ldsm4(&bfl[4], sBl + off + 16 * PG_LDB);
        }
#pragma unroll
        for (int n = 0; n < 4; n++) {
            mma16816(acc[n], afh, &bfh[n * 2]);
            mma16816(acc[n], afh, &bfl[n * 2]);
            mma16816(acc[n], afl, &bfh[n * 2]);
        }
    }

#pragma unroll
    for (int n = 0; n < 4; n++) {
        int i = i0 + wm * 16 + (lane >> 2);
        int t = t0 + wn * 32 + n * 8 + (lane & 3) * 2;
        if (t < 257) {
            g_P[((size_t)bh * 256 + i) * 257 + t]     = acc[n][0];
            g_P[((size_t)bh * 256 + i + 8) * 257 + t] = acc[n][2];
        }
        if (t + 1 < 257) {
            g_P[((size_t)bh * 256 + i) * 257 + t + 1]     = acc[n][1];
            g_P[((size_t)bh * 256 + i + 8) * 257 + t + 1] = acc[n][3];
        }
    }
}

// ============================================================================
// bias terms
// ============================================================================
__global__ __launch_bounds__(256) void cterm_kernel(const float* __restrict__ u)
{
    int row  = blockIdx.x * 8 + (threadIdx.x >> 5);
    int lane = threadIdx.x & 31;
    size_t o = (size_t)row * 64 + lane;
    float k0 = __bfloat162float(g_kh[o]) + __bfloat162float(g_kl[o]);
    float k1 = __bfloat162float(g_kh[o + 32]) + __bfloat162float(g_kl[o + 32]);
    float s = u[lane] * k0 + u[lane + 32] * k1;
#pragma unroll
    for (int of = 16; of; of >>= 1) s += __shfl_xor_sync(0xffffffffu, s, of);
    if (lane == 0) g_c[row] = s;
}

__global__ __launch_bounds__(256) void dterm_kernel(const float* __restrict__ v)
{
    int row = blockIdx.x * 8 + (threadIdx.x >> 5);
    if (row >= 16 * 257) return;
    int hh = row / 257, t = row % 257;
    int lane = threadIdx.x & 31;
    const float* src = g_RW + (size_t)((t + 768) & 1023) * 1024 + hh * 64;
    float s = v[lane] * src[lane] + v[lane + 32] * src[lane + 32];
#pragma unroll
    for (int of = 16; of; of >>= 1) s += __shfl_xor_sync(0xffffffffu, s, of);
    if (lane == 0) g_dt[row] = s;
}

// ============================================================================
// Fused windowed attention (mma). grid (4, 128), 256 threads (8 warps: 4m x 2n).
// smem: [qh|ph][ql|pl][bh][bl] 4 x 9216B + sS fp32 64 x 324.
// ============================================================================
#define AT_LDB 144
#define AT_SOFF (4 * 64 * AT_LDB)          // 36864
#define AT_SSTR 324
#define AT_SMEM (AT_SOFF + 64 * AT_SSTR * 4)  // 119808

__global__ __launch_bounds__(256) void attn_mma()
{
    extern __shared__ char sma[];
    uint32_t sQh = smem_u32(sma);           // later: probs hi
    uint32_t sQl = sQh + 64 * AT_LDB;       // later: probs lo
    uint32_t sBh = sQl + 64 * AT_LDB;       // k/v hi tile
    uint32_t sBl = sBh + 64 * AT_LDB;
    float* sS = (float*)(sma + AT_SOFF);

    int it = blockIdx.x, bh = blockIdx.y;
    int hh = bh & 15, bb = bh >> 4;
    int i0 = it * 64;
    int tid = threadIdx.x, lane = tid & 31, wid = tid >> 5;
    int wm = wid >> 1, wn = wid & 1;

    // load q hi/lo
#pragma unroll
    for (int l = 0; l < 2; l++) {
        int e = tid + l * 256;
        int row = e >> 3, c = e & 7;
        size_t qo = ((size_t)bh * 256 + i0 + row) * 64 + c * 8;
        *(uint4*)(sma + row * AT_LDB + c * 16) = *(const uint4*)&g_qh[qo];
        *(uint4*)(sma + 64 * AT_LDB + row * AT_LDB + c * 16) = *(const uint4*)&g_ql[qo];
    }

    // ---- phase 1: scores ----
    for (int jt = 0; jt < 5; jt++) {
        int jbase = i0 + jt * 64;
#pragma unroll
        for (int l = 0; l < 2; l++) {
            int e = tid + l * 256;
            int row = e >> 3, c = e & 7;
            size_t ko = ((size_t)bh * 512 + jbase + row) * 64 + c * 8;
            *(uint4*)(sma + 2 * 64 * AT_LDB + row * AT_LDB + c * 16) =
                *(const uint4*)&g_kh[ko];
            *(uint4*)(sma + 3 * 64 * AT_LDB + row * AT_LDB + c * 16) =
                *(const uint4*)&g_kl[ko];
        }
        __syncthreads();

        float sc[4][4];
#pragma unroll
        for (int n = 0; n < 4; n++)
#pragma unroll
            for (int j = 0; j < 4; j++) sc[n][j] = 0.f;

#pragma unroll
        for (int kk = 0; kk < 4; kk++) {
            uint32_t afh[4], afl[4];
            {
                int row = wm * 16 + (lane & 15);
                uint32_t off = (uint32_t)(row * AT_LDB + kk * 32 + (lane >> 4) * 16);
                ldsm4(afh, sQh + off);
                ldsm4(afl, sQl + off);
            }
            uint32_t bfh[8], bfl[8];
            {
                int n = wn * 32 + ((lane >> 4) * 8 + (lane & 7));
                uint32_t off = (uint32_t)(n * AT_LDB + kk * 32 + ((lane >> 3) & 1) * 16);
                ldsm4(&bfh[0], sBh + off);
                ldsm4(&bfh[4], sBh + off + 16 * AT_LDB);
                ldsm4(&bfl[0], sBl + off);
                ldsm4(&bfl[4], sBl + off + 16 * AT_LDB);
            }
#pragma unroll
            for (int n = 0; n < 4; n++) {
                mma16816(sc[n], afh, &bfh[n * 2]);
                mma16816(sc[n], afh, &bfl[n * 2]);
                mma16816(sc[n], afl, &bfh[n * 2]);
            }
        }

        // bias + mask + store to sS
#pragma unroll
        for (int n = 0; n < 4; n++) {
#pragma unroll
            for (int half = 0; half < 2; half++) {
                int il = wm * 16 + (lane >> 2) + half * 8;
                int ig = i0 + il;
#pragma unroll
                for (int e = 0; e < 2; e++) {
                    int jj = wn * 32 + n * 8 + (lane & 3) * 2 + e;
                    int delta = jt * 64 + jj - il;
                    float s = -1e30f;
                    if (delta >= 0 && delta <= 256) {
                        s = (sc[n][half * 2 + e]
                             + g_P[((size_t)bh * 256 + ig) * 257 + delta]
                             + g_c[(size_t)bh * 512 + jt * 64 + i0 + jj]
                             + g_dt[hh * 257 + delta]) * 0.125f;
                    }
                    sS[il * AT_SSTR + jt * 64 + jj] = s;
                }
            }
        }
        __syncthreads();
    }

    // ---- phase 2: softmax over 320 cols per row ----
    {
        int warp = wid, ln = lane;
        for (int r = warp; r < 64; r += 8) {
            float m = -1e30f;
            for (int c = ln; c < 320; c += 32) m = fmaxf(m, sS[r * AT_SSTR + c]);
#pragma unroll
            for (int o = 16; o; o >>= 1) m = fmaxf(m, __shfl_xor_sync(0xffffffffu, m, o));
            float sum = 0.f;
            for (int c = ln; c < 320; c += 32) {
                float e = __expf(sS[r * AT_SSTR + c] - m);
                sS[r * AT_SSTR + c] = e;
                sum += e;
            }
#pragma unroll
            for (int o = 16; o; o >>= 1) sum += __shfl_xor_sync(0xffffffffu, sum, o);
            float inv = 1.f / sum;
            for (int c = ln; c < 320; c += 32) sS[r * AT_SSTR + c] *= inv;
        }
    }
    __syncthreads();

    // ---- phase 3: O = P @ V ----
    float oa[4][4];
#pragma unroll
    for (int n = 0; n < 4; n++)
#pragma unroll
        for (int j = 0; j < 4; j++) oa[n][j] = 0.f;

    for (int jt = 0; jt < 5; jt++) {
        int jbase = i0 + jt * 64;
        // probs tile -> bf16 hi/lo in sQh/sQl region
#pragma unroll
        for (int l = 0; l < 8; l++) {
            int idx = tid + l * 256;
            int i = idx >> 5, jj2 = idx & 31;
            float a = sS[i * AT_SSTR + jt * 64 + jj2 * 2];
            float b = sS[i * AT_SSTR + jt * 64 + jj2 * 2 + 1];
            uint32_t H, L; pack2(a, b, H, L);
            *(uint32_t*)(sma + i * AT_LDB + jj2 * 4) = H;
            *(uint32_t*)(sma + 64 * AT_LDB + i * AT_LDB + jj2 * 4) = L;
        }
        // v tiles
#pragma unroll
        for (int l = 0; l < 2; l++) {
            int e = tid + l * 256;
            int row = e >> 3, c = e & 7;
            size_t vo = ((size_t)bh * 512 + jbase + row) * 64 + c * 8;
            *(uint4*)(sma + 2 * 64 * AT_LDB + row * AT_LDB + c * 16) =
                *(const uint4*)&g_vh[vo];
            *(uint4*)(sma + 3 * 64 * AT_LDB + row * AT_LDB + c * 16) =
                *(const uint4*)&g_vl[vo];
        }
        __syncthreads();

#pragma unroll
        for (int kk = 0; kk < 4; kk++) {
            uint32_t afh[4], afl[4];
            {
                int row = wm * 16 + (lane & 15);
                uint32_t off = (uint32_t)(row * AT_LDB + kk * 32 + (lane >> 4) * 16);
                ldsm4(afh, sQh + off);
                ldsm4(afl, sQl + off);
            }
            uint32_t bfh[8], bfl[8];
            {
                int g = lane >> 3;
                int kr = (g & 1) * 8 + (lane & 7);
                int nc = (g >> 1) * 8;
                uint32_t off = (uint32_t)((kk * 16 + kr) * AT_LDB
                                          + (wn * 32 + nc) * 2);
                ldsm4t(&bfh[0], sBh + off);
                ldsm4t(&bfh[4], sBh + off + 16 * 2);
                ldsm4t(&bfl[0], sBl + off);
                ldsm4t(&bfl[4], sBl + off + 16 * 2);
            }
#pragma unroll
            for (int n = 0; n < 4; n++) {
                mma16816(oa[n], afh, &bfh[n * 2]);
                mma16816(oa[n], afh, &bfl[n * 2]);
                mma16816(oa[n], afl, &bfh[n * 2]);
            }
        }
        __syncthreads();
    }

    // epilogue: O -> bf16 split rows of out-GEMM A buffer
#pragma unroll
    for (int n = 0; n < 4; n++) {
#pragma unroll
        for (int half = 0; half < 2; half++) {
            int ig = i0 + wm * 16 + (lane >> 2) + half * 8;
            int d  = wn * 32 + n * 8 + (lane & 3) * 2;
            uint32_t H, L;
            pack2(oa[n][half * 2 + 0], oa[n][half * 2 + 1], H, L);
            size_t o = ((size_t)bb * 256 + ig) * 1024 + hh * 64 + d;
            *(uint32_t*)&g_Ah[o] = H;
            *(uint32_t*)&g_Al[o] = L;
        }
    }
}

// ============================================================================
// kernel_launch
// ============================================================================
extern "C" void kernel_launch(void* const* d_in, const int* in_sizes, int n_in,
                              void* d_out, int out_size)
{
    const float* x    = (const float*)d_in[0];
    const float* h    = (const float*)d_in[1];
    const float* Wqkv = (const float*)d_in[2];
    const float* Wkr  = (const float*)d_in[3];
    const float* R    = (const float*)d_in[4];
    const float* u    = (const float*)d_in[5];
    const float* v    = (const float*)d_in[6];
    const float* Wout = (const float*)d_in[7];
    float* out = (float*)d_out;

    float* pRW = nullptr;
    __nv_bfloat16 *pAh = nullptr, *pAl = nullptr, *pBh = nullptr, *pBl = nullptr;
    cudaGetSymbolAddress((void**)&pRW, g_RW);
    cudaGetSymbolAddress((void**)&pAh, g_Ah);
    cudaGetSymbolAddress((void**)&pAl, g_Al);
    cudaGetSymbolAddress((void**)&pBh, g_Bh);
    cudaGetSymbolAddress((void**)&pBl, g_Bl);

    cudaFuncSetAttribute(mma_gemm, cudaFuncAttributeMaxDynamicSharedMemorySize,
                         MG_SMEM);
    cudaFuncSetAttribute(attn_mma, cudaFuncAttributeMaxDynamicSharedMemorySize,
                         AT_SMEM);

    // --- RW = R @ Wkr (fp32 + bf16 split) ---
    conv_split_T<<<dim3(32, 32), dim3(32, 8)>>>(Wkr, pBh, pBl, 1024);
    conv_split<<<1024, 256>>>((const float4*)R, (uint2*)pAh, (uint2*)pAl, 262144);
    mma_gemm<<<dim3(8, 8), 256, MG_SMEM>>>(pAh, pAl, pBh, pBl, pRW, 1024, 2);

    // --- qkv -> bf16 split q/k/v ---
    conv_split_T<<<dim3(96, 32), dim3(32, 8)>>>(Wqkv, pBh, pBl, 3072);
    conv_split_cat<<<4096, 256>>>(x, h, (uint2*)pAh, (uint2*)pAl);
    mma_gemm<<<dim3(24, 32), 256, MG_SMEM>>>(pAh, pAl, pBh, pBl, nullptr, 0, 1);

    // --- P + bias terms ---
    p_gemm_mma<<<dim3(5, 4, 128), 256>>>();
    cterm_kernel<<<8192, 256>>>(u);
    dterm_kernel<<<514, 256>>>(v);

    // --- fused attention (writes bf16-split O into g_Ah/g_Al) ---
    attn_mma<<<dim3(4, 128), 256, AT_SMEM>>>();

    // --- out = O @ Wout ---
    conv_split_T<<<dim3(32, 32), dim3(32, 8)>>>(Wout, pBh, pBl, 1024);
    mma_gemm<<<dim3(8, 16), 256, MG_SMEM>>>(pAh, pAl, pBh, pBl, out, 1024, 0);
}

// round 5
// speedup vs baseline: 2.7831x; 1.0705x over previous
#include <cuda_runtime.h>
#include <cuda_bf16.h>
#include <cstdint>

// ============================================================================
// B=8, N=256, M=256, T=512, H=16, D=64, DIM=1024.
// Window: j in [i, i+256]; delta = j-i; Ppad[bh][i][delta+64] holds
// 0.125*(q.RW + c + dt) for valid delta, -1e30 otherwise (q pre-scaled).
// ============================================================================

__device__ float g_RW [1024u * 1024u];                 // fp32 (for dterm)
__device__ __nv_bfloat16 g_RWh[1024u * 1024u];
__device__ __nv_bfloat16 g_RWl[1024u * 1024u];
__device__ __nv_bfloat16 g_qh[8u*16u*256u*64u], g_ql[8u*16u*256u*64u];
__device__ __nv_bfloat16 g_kh[8u*16u*512u*64u], g_kl[8u*16u*512u*64u];
__device__ __nv_bfloat16 g_vh[8u*16u*512u*64u], g_vl[8u*16u*512u*64u];
__device__ float g_Pp[8u * 16u * 256u * 384u];         // padded biased scores
__device__ float g_c [8u * 16u * 512u];
__device__ float g_dt[16u * 257u];

__device__ __nv_bfloat16 g_Ah [4096u * 1024u], g_Al [4096u * 1024u];  // cat(h,x)
__device__ __nv_bfloat16 g_ARh[1024u * 1024u], g_ARl[1024u * 1024u];  // R
__device__ __nv_bfloat16 g_Bh [3072u * 1024u], g_Bl [3072u * 1024u];  // Wqkv^T
__device__ __nv_bfloat16 g_BKh[1024u * 1024u], g_BKl[1024u * 1024u];  // Wkr^T
__device__ __nv_bfloat16 g_BOh[1024u * 1024u], g_BOl[1024u * 1024u];  // Wout^T
__device__ __nv_bfloat16 g_Oh [2048u * 1024u], g_Ol [2048u * 1024u];  // attn out

// ============================================================================
// PTX helpers
// ============================================================================
__device__ __forceinline__ uint32_t smem_u32(const void* p) {
    uint32_t a;
    asm("{ .reg .u64 t; cvta.to.shared.u64 t, %1; cvt.u32.u64 %0, t; }"
        : "=r"(a) : "l"(p));
    return a;
}
__device__ __forceinline__ void cp16(uint32_t saddr, const void* g) {
    asm volatile("cp.async.cg.shared.global [%0], [%1], 16;"
                 :: "r"(saddr), "l"(g) : "memory");
}
#define CP_COMMIT() asm volatile("cp.async.commit_group;" ::: "memory")
#define CP_WAIT1()  asm volatile("cp.async.wait_group 1;" ::: "memory")
#define CP_WAIT0()  asm volatile("cp.async.wait_group 0;" ::: "memory")

__device__ __forceinline__ void ldsm4(uint32_t* r, uint32_t addr) {
    asm volatile("ldmatrix.sync.aligned.m8n8.x4.shared.b16 {%0,%1,%2,%3}, [%4];"
                 : "=r"(r[0]), "=r"(r[1]), "=r"(r[2]), "=r"(r[3]) : "r"(addr));
}
__device__ __forceinline__ void ldsm4t(uint32_t* r, uint32_t addr) {
    asm volatile("ldmatrix.sync.aligned.m8n8.x4.trans.shared.b16 {%0,%1,%2,%3}, [%4];"
                 : "=r"(r[0]), "=r"(r[1]), "=r"(r[2]), "=r"(r[3]) : "r"(addr));
}
__device__ __forceinline__ void mma16816(float* c, const uint32_t* a,
                                         const uint32_t* b) {
    asm volatile(
        "mma.sync.aligned.m16n8k16.row.col.f32.bf16.bf16.f32 "
        "{%0,%1,%2,%3}, {%4,%5,%6,%7}, {%8,%9}, {%0,%1,%2,%3};"
        : "+f"(c[0]), "+f"(c[1]), "+f"(c[2]), "+f"(c[3])
        : "r"(a[0]), "r"(a[1]), "r"(a[2]), "r"(a[3]), "r"(b[0]), "r"(b[1]));
}

__device__ __forceinline__ unsigned short bfb(__nv_bfloat16 x) {
    return *reinterpret_cast<unsigned short*>(&x);
}
__device__ __forceinline__ void pack2(float a, float b, uint32_t& H, uint32_t& L) {
    __nv_bfloat16 ah = __float2bfloat16(a), bh2 = __float2bfloat16(b);
    __nv_bfloat16 al = __float2bfloat16(a - __bfloat162float(ah));
    __nv_bfloat16 bl = __float2bfloat16(b - __bfloat162float(bh2));
    H = (uint32_t)bfb(ah) | ((uint32_t)bfb(bh2) << 16);
    L = (uint32_t)bfb(al) | ((uint32_t)bfb(bl) << 16);
}

// ============================================================================
// Dense mma GEMM (unchanged structure). mode 0: fp32 C. mode 1: qkv scatter
// (q pre-scaled by 0.125). mode 2: fp32 C + bf16 split to g_RWh/l.
// ============================================================================
#define MG_ARR 10240
#define MG_STG (4 * MG_ARR)
#define MG_SMEM (2 * MG_STG)

__device__ __forceinline__ void qkv_scatter(int gr, int gc, float v0, float v1) {
    int b = gr >> 9, tt = gr & 511;
    int sec = gc >> 10, c2 = gc & 1023, hh = c2 >> 6, d = c2 & 63;
    if (sec == 0) {
        if (tt >= 256) {
            uint32_t H, L; pack2(v0 * 0.125f, v1 * 0.125f, H, L);
            size_t o = (((size_t)b * 16 + hh) * 256 + (tt - 256)) * 64 + d;
            *(uint32_t*)&g_qh[o] = H; *(uint32_t*)&g_ql[o] = L;
        }
    } else {
        uint32_t H, L; pack2(v0, v1, H, L);
        size_t o = (((size_t)b * 16 + hh) * 512 + tt) * 64 + d;
        if (sec == 1) { *(uint32_t*)&g_kh[o] = H; *(uint32_t*)&g_kl[o] = L; }
        else          { *(uint32_t*)&g_vh[o] = H; *(uint32_t*)&g_vl[o] = L; }
    }
}

__global__ __launch_bounds__(256) void mma_gemm(
    const __nv_bfloat16* __restrict__ Ah, const __nv_bfloat16* __restrict__ Al,
    const __nv_bfloat16* __restrict__ Bh, const __nv_bfloat16* __restrict__ Bl,
    float* __restrict__ C, int ldc, int mode)
{
    int bx = blockIdx.x, by = blockIdx.y;
    if (mode == 1 && bx < 8 && (by & 3) < 2) return;

    extern __shared__ char smc[];
    uint32_t sb = smem_u32(smc);
    int tid = threadIdx.x, lane = tid & 31, wid = tid >> 5;
    int wm = wid >> 2, wn = wid & 3;

    const __nv_bfloat16* gA[2] = { Ah, Al };
    const __nv_bfloat16* gB[2] = { Bh, Bl };

    auto load_stage = [&](int s, int kt) {
#pragma unroll
        for (int l = 0; l < 8; l++) {
            int idx = tid + l * 256;
            int arr = idx >> 9, e = idx & 511;
            int row = e >> 2, c = e & 3;
            const __nv_bfloat16* gp = (arr < 2)
                ? gA[arr] + (size_t)(by * 128 + row) * 1024 + kt * 32 + c * 8
                : gB[arr - 2] + (size_t)(bx * 128 + row) * 1024 + kt * 32 + c * 8;
            cp16(sb + s * MG_STG + arr * MG_ARR + (uint32_t)(row * 80 + c * 16), gp);
        }
        CP_COMMIT();
    };

    float acc[16][4];
#pragma unroll
    for (int i = 0; i < 16; i++)
#pragma unroll
        for (int j = 0; j < 4; j++) acc[i][j] = 0.f;

    load_stage(0, 0);

    for (int kt = 0; kt < 32; kt++) {
        if (kt + 1 < 32) { load_stage((kt + 1) & 1, kt + 1); CP_WAIT1(); }
        else             { CP_WAIT0(); }
        __syncthreads();

        uint32_t stg = sb + (kt & 1) * MG_STG;
#pragma unroll
        for (int kk = 0; kk < 2; kk++) {
            uint32_t afh[4][4], afl[4][4];
            {
                int row = wm * 64 + (lane & 15);
                int c   = kk * 2 + (lane >> 4);
                uint32_t off = (uint32_t)(row * 80 + c * 16);
#pragma unroll
                for (int t = 0; t < 4; t++) {
                    ldsm4(afh[t], stg + 0 * MG_ARR + off + t * (16 * 80));
                    ldsm4(afl[t], stg + 1 * MG_ARR + off + t * (16 * 80));
                }
            }
            uint32_t bfh[8], bfl[8];
            {
                int n = wn * 32 + ((lane >> 4) * 8 + (lane & 7));
                int c = kk * 2 + ((lane >> 3) & 1);
                uint32_t off = (uint32_t)(n * 80 + c * 16);
                ldsm4(&bfh[0], stg + 2 * MG_ARR + off);
                ldsm4(&bfh[4], stg + 2 * MG_ARR + off + 16 * 80);
                ldsm4(&bfl[0], stg + 3 * MG_ARR + off);
                ldsm4(&bfl[4], stg + 3 * MG_ARR + off + 16 * 80);
            }
#pragma unroll
            for (int t = 0; t < 4; t++)
#pragma unroll
                for (int n = 0; n < 4; n++) {
                    float* cc = acc[t * 4 + n];
                    mma16816(cc, afh[t], &bfh[n * 2]);
                    mma16816(cc, afh[t], &bfl[n * 2]);
                    mma16816(cc, afl[t], &bfh[n * 2]);
                }
        }
        __syncthreads();
    }

#pragma unroll
    for (int t = 0; t < 4; t++)
#pragma unroll
        for (int n = 0; n < 4; n++) {
            int gr = by * 128 + wm * 64 + t * 16 + (lane >> 2);
            int gc = bx * 128 + wn * 32 + n * 8 + (lane & 3) * 2;
            float* cc = acc[t * 4 + n];
            if (mode == 0) {
                *(float2*)&C[(size_t)gr * ldc + gc]       = make_float2(cc[0], cc[1]);
                *(float2*)&C[(size_t)(gr + 8) * ldc + gc] = make_float2(cc[2], cc[3]);
            } else if (mode == 2) {
                *(float2*)&C[(size_t)gr * ldc + gc]       = make_float2(cc[0], cc[1]);
                *(float2*)&C[(size_t)(gr + 8) * ldc + gc] = make_float2(cc[2], cc[3]);
                uint32_t H, L;
                pack2(cc[0], cc[1], H, L);
                *(uint32_t*)&g_RWh[(size_t)gr * 1024 + gc] = H;
                *(uint32_t*)&g_RWl[(size_t)gr * 1024 + gc] = L;
                pack2(cc[2], cc[3], H, L);
                *(uint32_t*)&g_RWh[(size_t)(gr + 8) * 1024 + gc] = H;
                *(uint32_t*)&g_RWl[(size_t)(gr + 8) * 1024 + gc] = L;
            } else {
                qkv_scatter(gr, gc, cc[0], cc[1]);
                qkv_scatter(gr + 8, gc, cc[2], cc[3]);
            }
        }
}

// ============================================================================
// Conversions (merged)
// ============================================================================
__device__ __forceinline__ void split4(float4 v, uint2& H, uint2& L) {
    uint32_t h0, l0, h1, l1;
    pack2(v.x, v.y, h0, l0);
    pack2(v.z, v.w, h1, l1);
    H.x = h0; H.y = h1; L.x = l0; L.y = l1;
}

// all three weight transposes in one launch: z=0 Wqkv, z=1 Wkr, z=2 Wout
__global__ __launch_bounds__(256) void conv_all_T(
    const float* __restrict__ Wqkv, const float* __restrict__ Wkr,
    const float* __restrict__ Wout)
{
    int z = blockIdx.z;
    const float* W; __nv_bfloat16 *Th, *Tl; int N;
    if (z == 0)      { W = Wqkv; Th = g_Bh;  Tl = g_Bl;  N = 3072; }
    else if (z == 1) { if (blockIdx.x >= 32) return;
                       W = Wkr;  Th = g_BKh; Tl = g_BKl; N = 1024; }
    else             { if (blockIdx.x >= 32) return;
                       W = Wout; Th = g_BOh; Tl = g_BOl; N = 1024; }

    __shared__ float ts[32][33];
    int n0 = blockIdx.x * 32, k0 = blockIdx.y * 32;
    int tx = threadIdx.x & 31, ty = threadIdx.x >> 5;
#pragma unroll
    for (int r = 0; r < 32; r += 8)
        ts[ty + r][tx] = W[(size_t)(k0 + ty + r) * N + n0 + tx];
    __syncthreads();
#pragma unroll
    for (int r = 0; r < 32; r += 8) {
        float v = ts[tx][ty + r];
        __nv_bfloat16 hh = __float2bfloat16(v);
        __nv_bfloat16 ll = __float2bfloat16(v - __bfloat162float(hh));
        size_t o = (size_t)(n0 + ty + r) * 1024 + k0 + tx;
        Th[o] = hh; Tl[o] = ll;
    }
}

// cat(h,x) -> g_Ah/g_Al (blocks 0..4095); R -> g_ARh/g_ARl (4096..5119)
__global__ __launch_bounds__(256) void conv_A(
    const float* __restrict__ x, const float* __restrict__ h,
    const float* __restrict__ R)
{
    int blk = blockIdx.x;
    if (blk < 4096) {
        int i = blk * 256 + threadIdx.x;
        int row = i >> 8, c4 = i & 255;
        int b = row >> 9, t = row & 511;
        const float4* src = (const float4*)((t < 256)
            ? (h + ((size_t)b * 256 + t) * 1024)
            : (x + ((size_t)b * 256 + (t - 256)) * 1024));
        uint2 H, L;
        split4(src[c4], H, L);
        ((uint2*)g_Ah)[i] = H; ((uint2*)g_Al)[i] = L;
    } else {
        int i = (blk - 4096) * 256 + threadIdx.x;
        uint2 H, L;
        split4(((const float4*)R)[i], H, L);
        ((uint2*)g_ARh)[i] = H; ((uint2*)g_ARl)[i] = L;
    }
}

// cterm (blocks 0..8191) + dterm (8192..8705)
__global__ __launch_bounds__(256) void cdterm(const float* __restrict__ u,
                                              const float* __restrict__ v)
{
    int blk = blockIdx.x;
    int lane = threadIdx.x & 31;
    if (blk < 8192) {
        int row = blk * 8 + (threadIdx.x >> 5);
        size_t o = (size_t)row * 64 + lane;
        float k0 = __bfloat162float(g_kh[o]) + __bfloat162float(g_kl[o]);
        float k1 = __bfloat162float(g_kh[o + 32]) + __bfloat162float(g_kl[o + 32]);
        float s = u[lane] * k0 + u[lane + 32] * k1;
#pragma unroll
        for (int of = 16; of; of >>= 1) s += __shfl_xor_sync(0xffffffffu, s, of);
        if (lane == 0) g_c[row] = s;
    } else {
        int row = (blk - 8192) * 8 + (threadIdx.x >> 5);
        if (row >= 16 * 257) return;
        int hh = row / 257, t = row % 257;
        const float* src = g_RW + (size_t)((t + 768) & 1023) * 1024 + hh * 64;
        float s = v[lane] * src[lane] + v[lane + 32] * src[lane + 32];
#pragma unroll
        for (int of = 16; of; of >>= 1) s += __shfl_xor_sync(0xffffffffu, s, of);
        if (lane == 0) g_dt[row] = s;
    }
}

// ============================================================================
// P GEMM v2 -> Ppad[bh][i][idx], idx = delta + 64 in [0,384).
// grid (6 idx-tiles, 4 i-tiles, 128 bh). Tile 0 is pure -1e30 fill.
// Epilogue folds 0.125*(c + dt); q already pre-scaled.
// ============================================================================
#define PG_LDB 144
__global__ __launch_bounds__(256) void p_gemm2()
{
    __shared__ char sm2[4 * 64 * PG_LDB];
    int tt = blockIdx.x, it = blockIdx.y, bh = blockIdx.z;
    int hh = bh & 15;
    int i0 = it * 64;
    int tid = threadIdx.x, lane = tid & 31, wid = tid >> 5;

    if (tt == 0) {
        for (int e = tid; e < 4096; e += 256) {
            int row = e >> 6, idx = e & 63;
            g_Pp[((size_t)bh * 256 + i0 + row) * 384 + idx] = -1e30f;
        }
        return;
    }

    uint32_t sb = smem_u32(sm2);
    uint32_t sQh = sb, sQl = sb + 9216, sBh = sb + 18432, sBl = sb + 27648;
    int wm = wid >> 1, wn = wid & 1;

#pragma unroll
    for (int l = 0; l < 2; l++) {
        int e = tid + l * 256;
        int row = e >> 3, c = e & 7;
        size_t qo = ((size_t)bh * 256 + i0 + row) * 64 + c * 8;
        *(uint4*)(sm2 + row * PG_LDB + c * 16) = *(const uint4*)&g_qh[qo];
        *(uint4*)(sm2 + 9216 + row * PG_LDB + c * 16) = *(const uint4*)&g_ql[qo];
        int t = (tt - 1) * 64 + row;
        int rr = (t + 768) & 1023;
        size_t bo = (size_t)rr * 1024 + hh * 64 + c * 8;
        *(uint4*)(sm2 + 18432 + row * PG_LDB + c * 16) = *(const uint4*)&g_RWh[bo];
        *(uint4*)(sm2 + 27648 + row * PG_LDB + c * 16) = *(const uint4*)&g_RWl[bo];
    }
    __syncthreads();

    float acc[4][4];
#pragma unroll
    for (int n = 0; n < 4; n++)
#pragma unroll
        for (int j = 0; j < 4; j++) acc[n][j] = 0.f;

#pragma unroll
    for (int kk = 0; kk < 4; kk++) {
        uint32_t afh[4], afl[4];
        {
            int row = wm * 16 + (lane & 15);
            uint32_t off = (uint32_t)(row * PG_LDB + kk * 32 + (lane >> 4) * 16);
            ldsm4(afh, sQh + off);
            ldsm4(afl, sQl + off);
        }
        uint32_t bfh[8], bfl[8];
        {
            int n = wn * 32 + ((lane >> 4) * 8 + (lane & 7));
            uint32_t off = (uint32_t)(n * PG_LDB + kk * 32 + ((lane >> 3) & 1) * 16);
            ldsm4(&bfh[0], sBh + off);
            ldsm4(&bfh[4], sBh + off + 16 * PG_LDB);
            ldsm4(&bfl[0], sBl + off);
            ldsm4(&bfl[4], sBl + off + 16 * PG_LDB);
        }
#pragma unroll
        for (int n = 0; n < 4; n++) {
            mma16816(acc[n], afh, &bfh[n * 2]);
            mma16816(acc[n], afh, &bfl[n * 2]);
            mma16816(acc[n], afl, &bfh[n * 2]);
        }
    }

#pragma unroll
    for (int n = 0; n < 4; n++) {
        int tl = wn * 32 + n * 8 + (lane & 3) * 2;
#pragma unroll
        for (int half = 0; half < 2; half++) {
            int ii = i0 + wm * 16 + (lane >> 2) + half * 8;
#pragma unroll
            for (int e = 0; e < 2; e++) {
                int t = (tt - 1) * 64 + tl + e;
                float a = acc[n][half * 2 + e];
                float val = -1e30f;
                if (t < 257)
                    val = a + 0.125f * (g_c[(size_t)bh * 512 + ii + t]
                                        + g_dt[hh * 257 + t]);
                g_Pp[((size_t)bh * 256 + ii) * 384 + t + 64] = val;
            }
        }
    }
}

// ============================================================================
// Fused attention v2: register softmax, single-load bias, PV from reg frags.
// grid (4 i-tiles, 128 bh), 256 threads = 8 warps (wm 0..3 x wn 0..1).
// ============================================================================
#define AT_LDB 144
__global__ __launch_bounds__(256) void attn_mma2()
{
    __shared__ char sma[36864 + 1024];
    uint32_t sb = smem_u32(sma);
    uint32_t sQh = sb, sQl = sb + 9216;
    uint32_t sKh = sb + 18432, sKl = sb + 27648;
    float* sRed = (float*)(sma + 36864);   // [64][4]
    float* sO   = (float*)sma;             // overlay (stride 66), 16.9KB

    int it = blockIdx.x, bh = blockIdx.y;
    int hh = bh & 15, bb = bh >> 4;
    int i0 = it * 64;
    int tid = threadIdx.x, lane = tid & 31, wid = tid >> 5;
    int wm = wid >> 1, wn = wid & 1;

    // q hi/lo -> smem
#pragma unroll
    for (int l = 0; l < 2; l++) {
        int e = tid + l * 256, row = e >> 3, c = e & 7;
        size_t qo = ((size_t)bh * 256 + i0 + row) * 64 + c * 8;
        *(uint4*)(sma + row * AT_LDB + c * 16) = *(const uint4*)&g_qh[qo];
        *(uint4*)(sma + 9216 + row * AT_LDB + c * 16) = *(const uint4*)&g_ql[qo];
    }

    float sc[5][4][4];
#pragma unroll
    for (int jt = 0; jt < 5; jt++)
#pragma unroll
        for (int n = 0; n < 4; n++)
#pragma unroll
            for (int j = 0; j < 4; j++) sc[jt][n][j] = 0.f;

    // ---- phase 1: scores into registers ----
#pragma unroll
    for (int jt = 0; jt < 5; jt++) {
#pragma unroll
        for (int l = 0; l < 2; l++) {
            int e = tid + l * 256, row = e >> 3, c = e & 7;
            size_t ko = ((size_t)bh * 512 + i0 + jt * 64 + row) * 64 + c * 8;
            *(uint4*)(sma + 18432 + row * AT_LDB + c * 16) = *(const uint4*)&g_kh[ko];
            *(uint4*)(sma + 27648 + row * AT_LDB + c * 16) = *(const uint4*)&g_kl[ko];
        }
        __syncthreads();
#pragma unroll
        for (int kk = 0; kk < 4; kk++) {
            uint32_t afh[4], afl[4];
            {
                int row = wm * 16 + (lane & 15);
                uint32_t off = (uint32_t)(row * AT_LDB + kk * 32 + (lane >> 4) * 16);
                ldsm4(afh, sQh + off);
                ldsm4(afl, sQl + off);
            }
            uint32_t bfh[8], bfl[8];
            {
                int n = wn * 32 + ((lane >> 4) * 8 + (lane & 7));
                uint32_t off = (uint32_t)(n * AT_LDB + kk * 32 + ((lane >> 3) & 1) * 16);
                ldsm4(&bfh[0], sKh + off);
                ldsm4(&bfh[4], sKh + off + 16 * AT_LDB);
                ldsm4(&bfl[0], sKl + off);
                ldsm4(&bfl[4], sKl + off + 16 * AT_LDB);
            }
#pragma unroll
            for (int n = 0; n < 4; n++) {
                mma16816(sc[jt][n], afh, &bfh[n * 2]);
                mma16816(sc[jt][n], afh, &bfl[n * 2]);
                mma16816(sc[jt][n], afl, &bfh[n * 2]);
            }
        }
        __syncthreads();
    }

    // ---- phase 2: bias + softmax in registers ----
    int r1 = wm * 16 + (lane >> 2), r2 = r1 + 8;
    const float* P1 = &g_Pp[((size_t)bh * 256 + i0 + r1) * 384 + 64 - r1];
    const float* P2 = &g_Pp[((size_t)bh * 256 + i0 + r2) * 384 + 64 - r2];
    float m1 = -1e30f, m2 = -1e30f;
#pragma unroll
    for (int jt = 0; jt < 5; jt++)
#pragma unroll
        for (int n = 0; n < 4; n++) {
            int col = jt * 64 + wn * 32 + n * 8 + (lane & 3) * 2;
            sc[jt][n][0] += P1[col];     sc[jt][n][1] += P1[col + 1];
            sc[jt][n][2] += P2[col];     sc[jt][n][3] += P2[col + 1];
            m1 = fmaxf(m1, fmaxf(sc[jt][n][0], sc[jt][n][1]));
            m2 = fmaxf(m2, fmaxf(sc[jt][n][2], sc[jt][n][3]));
        }
    m1 = fmaxf(m1, __shfl_xor_sync(0xffffffffu, m1, 1));
    m1 = fmaxf(m1, __shfl_xor_sync(0xffffffffu, m1, 2));
    m2 = fmaxf(m2, __shfl_xor_sync(0xffffffffu, m2, 1));
    m2 = fmaxf(m2, __shfl_xor_sync(0xffffffffu, m2, 2));
    if ((lane & 3) == 0) { sRed[r1 * 4 + wn] = m1; sRed[r2 * 4 + wn] = m2; }
    __syncthreads();
    m1 = fmaxf(sRed[r1 * 4 + 0], sRed[r1 * 4 + 1]);
    m2 = fmaxf(sRed[r2 * 4 + 0], sRed[r2 * 4 + 1]);

    float s1 = 0.f, s2 = 0.f;
#pragma unroll
    for (int jt = 0; jt < 5; jt++)
#pragma unroll
        for (int n = 0; n < 4; n++) {
            float e0 = __expf(sc[jt][n][0] - m1);
            float e1 = __expf(sc[jt][n][1] - m1);
            float e2 = __expf(sc[jt][n][2] - m2);
            float e3 = __expf(sc[jt][n][3] - m2);
            sc[jt][n][0] = e0; sc[jt][n][1] = e1;
            sc[jt][n][2] = e2; sc[jt][n][3] = e3;
            s1 += e0 + e1; s2 += e2 + e3;
        }
    s1 += __shfl_xor_sync(0xffffffffu, s1, 1);
    s1 += __shfl_xor_sync(0xffffffffu, s1, 2);
    s2 += __shfl_xor_sync(0xffffffffu, s2, 1);
    s2 += __shfl_xor_sync(0xffffffffu, s2, 2);
    if ((lane & 3) == 0) { sRed[r1 * 4 + 2 + wn] = s1; sRed[r2 * 4 + 2 + wn] = s2; }
    __syncthreads();
    float inv1 = 1.f / (sRed[r1 * 4 + 2] + sRed[r1 * 4 + 3]);
    float inv2 = 1.f / (sRed[r2 * 4 + 2] + sRed[r2 * 4 + 3]);

    // probs -> bf16 hi/lo A-fragments (C frag layout == A frag layout)
    uint32_t ph[5][2][4], pl[5][2][4];
#pragma unroll
    for (int jt = 0; jt < 5; jt++)
#pragma unroll
        for (int t = 0; t < 2; t++) {
            pack2(sc[jt][2*t][0] * inv1, sc[jt][2*t][1] * inv1,
                  ph[jt][t][0], pl[jt][t][0]);
            pack2(sc[jt][2*t][2] * inv2, sc[jt][2*t][3] * inv2,
                  ph[jt][t][1], pl[jt][t][1]);
            pack2(sc[jt][2*t+1][0] * inv1, sc[jt][2*t+1][1] * inv1,
                  ph[jt][t][2], pl[jt][t][2]);
            pack2(sc[jt][2*t+1][2] * inv2, sc[jt][2*t+1][3] * inv2,
                  ph[jt][t][3], pl[jt][t][3]);
        }

    // ---- phase 3: O = P @ V ----
    float oacc[8][4];
#pragma unroll
    for (int n = 0; n < 8; n++)
#pragma unroll
        for (int j = 0; j < 4; j++) oacc[n][j] = 0.f;

#pragma unroll
    for (int jt = 0; jt < 5; jt++) {
#pragma unroll
        for (int l = 0; l < 2; l++) {
            int e = tid + l * 256, row = e >> 3, c = e & 7;
            size_t vo = ((size_t)bh * 512 + i0 + jt * 64 + row) * 64 + c * 8;
            *(uint4*)(sma + 18432 + row * AT_LDB + c * 16) = *(const uint4*)&g_vh[vo];
            *(uint4*)(sma + 27648 + row * AT_LDB + c * 16) = *(const uint4*)&g_vl[vo];
        }
        __syncthreads();
#pragma unroll
        for (int t = 0; t < 2; t++) {
            uint32_t bfh[16], bfl[16];
            int g = lane >> 3;
            int kr = (g & 1) * 8 + (lane & 7);
            int nc = (g >> 1) * 8;
            uint32_t base = (uint32_t)((wn * 32 + t * 16 + kr) * AT_LDB + nc * 2);
#pragma unroll
            for (int dd = 0; dd < 4; dd++) {
                ldsm4t(&bfh[dd * 4], sKh + base + dd * 32);
                ldsm4t(&bfl[dd * 4], sKl + base + dd * 32);
            }
#pragma unroll
            for (int n = 0; n < 8; n++) {
                const uint32_t* bh_ = &bfh[(n >> 1) * 4 + (n & 1) * 2];
                const uint32_t* bl_ = &bfl[(n >> 1) * 4 + (n & 1) * 2];
                mma16816(oacc[n], ph[jt][t], bh_);
                mma16816(oacc[n], ph[jt][t], bl_);
                mma16816(oacc[n], pl[jt][t], bh_);
            }
        }
        __syncthreads();
    }

    // ---- cross-warp (wn) O reduction, then store bf16 split ----
    if (wn == 0) {
#pragma unroll
        for (int n = 0; n < 8; n++) {
            int c0 = n * 8 + (lane & 3) * 2;
            sO[r1 * 66 + c0]     = oacc[n][0];
            sO[r1 * 66 + c0 + 1] = oacc[n][1];
            sO[r2 * 66 + c0]     = oacc[n][2];
            sO[r2 * 66 + c0 + 1] = oacc[n][3];
        }
    }
    __syncthreads();
    if (wn == 1) {
#pragma unroll
        for (int n = 0; n < 8; n++) {
            int c0 = n * 8 + (lane & 3) * 2;
            float a0 = oacc[n][0] + sO[r1 * 66 + c0];
            float a1 = oacc[n][1] + sO[r1 * 66 + c0 + 1];
            float a2 = oacc[n][2] + sO[r2 * 66 + c0];
            float a3 = oacc[n][3] + sO[r2 * 66 + c0 + 1];
            uint32_t H, L;
            pack2(a0, a1, H, L);
            size_t o1 = ((size_t)bb * 256 + i0 + r1) * 1024 + hh * 64 + c0;
            *(uint32_t*)&g_Oh[o1] = H; *(uint32_t*)&g_Ol[o1] = L;
            pack2(a2, a3, H, L);
            size_t o2 = ((size_t)bb * 256 + i0 + r2) * 1024 + hh * 64 + c0;
            *(uint32_t*)&g_Oh[o2] = H; *(uint32_t*)&g_Ol[o2] = L;
        }
    }
}

// ============================================================================
// kernel_launch
// ============================================================================
extern "C" void kernel_launch(void* const* d_in, const int* in_sizes, int n_in,
                              void* d_out, int out_size)
{
    const float* x    = (const float*)d_in[0];
    const float* h    = (const float*)d_in[1];
    const float* Wqkv = (const float*)d_in[2];
    const float* Wkr  = (const float*)d_in[3];
    const float* R    = (const float*)d_in[4];
    const float* u    = (const float*)d_in[5];
    const float* v    = (const float*)d_in[6];
    const float* Wout = (const float*)d_in[7];
    float* out = (float*)d_out;

    float* pRW = nullptr;
    __nv_bfloat16 *pAh, *pAl, *pARh, *pARl, *pBh, *pBl, *pBKh, *pBKl,
                  *pBOh, *pBOl, *pOh, *pOl;
    cudaGetSymbolAddress((void**)&pRW,  g_RW);
    cudaGetSymbolAddress((void**)&pAh,  g_Ah);
    cudaGetSymbolAddress((void**)&pAl,  g_Al);
    cudaGetSymbolAddress((void**)&pARh, g_ARh);
    cudaGetSymbolAddress((void**)&pARl, g_ARl);
    cudaGetSymbolAddress((void**)&pBh,  g_Bh);
    cudaGetSymbolAddress((void**)&pBl,  g_Bl);
    cudaGetSymbolAddress((void**)&pBKh, g_BKh);
    cudaGetSymbolAddress((void**)&pBKl, g_BKl);
    cudaGetSymbolAddress((void**)&pBOh, g_BOh);
    cudaGetSymbolAddress((void**)&pBOl, g_BOl);
    cudaGetSymbolAddress((void**)&pOh,  g_Oh);
    cudaGetSymbolAddress((void**)&pOl,  g_Ol);

    cudaFuncSetAttribute(mma_gemm, cudaFuncAttributeMaxDynamicSharedMemorySize,
                         MG_SMEM);

    // conversions
    conv_all_T<<<dim3(96, 32, 3), 256>>>(Wqkv, Wkr, Wout);
    conv_A<<<5120, 256>>>(x, h, R);

    // RW = R @ Wkr (fp32 + bf16 split)
    mma_gemm<<<dim3(8, 8), 256, MG_SMEM>>>(pARh, pARl, pBKh, pBKl, pRW, 1024, 2);

    // qkv (q pre-scaled by 0.125)
    mma_gemm<<<dim3(24, 32), 256, MG_SMEM>>>(pAh, pAl, pBh, pBl, nullptr, 0, 1);

    // bias terms, then P (folds c + dt, writes padded -1e30 layout)
    cdterm<<<8706, 256>>>(u, v);
    p_gemm2<<<dim3(6, 4, 128), 256>>>();

    // fused attention
    attn_mma2<<<dim3(4, 128), 256>>>();

    // out = O @ Wout
    mma_gemm<<<dim3(8, 16), 256, MG_SMEM>>>(pOh, pOl, pBOh, pBOl, out, 1024, 0);
}